// round 5
// baseline (speedup 1.0000x reference)
#include <cuda_runtime.h>

static constexpr int NNODES = 10000;
static constexpr int NE     = 640000;
static constexpr int DIN    = 128;
static constexpr int DHID   = 256;
static constexpr int DOUT   = 64;

// ---- scratch (__device__ globals: allocation-free rule) ----
__device__ int   g_cnt[NNODES];
__device__ int   g_off[NNODES + 1];
__device__ int   g_rank[NE];
__device__ int2  g_edges[NE];            // (src, w bits) grouped by dst
__device__ float g_hN[NNODES * DIN];     // layer-1 mean aggregate (normalized)
__device__ float g_x [NNODES * DHID];    // layer-1 output (post relu)
__device__ float g_y [NNODES * DOUT];    // x @ W2_bot

// ---------------------------------------------------------------------------
// CSR build: zero -> count(+rank) -> scan -> fill(no atomics)
// ---------------------------------------------------------------------------
__global__ void zero_cnt_kernel() {
    int i = blockIdx.x * blockDim.x + threadIdx.x;
    if (i < NNODES) g_cnt[i] = 0;
}

__global__ void count_rank_kernel(const int* __restrict__ dst) {
    int e = blockIdx.x * blockDim.x + threadIdx.x;
    if (e < NE) g_rank[e] = atomicAdd(&g_cnt[dst[e]], 1);
}

__global__ void scan_kernel() {
    __shared__ int sh[1024];
    constexpr int CH = 10;                // 1024*10 >= 10000
    int t = threadIdx.x;
    int base = t * CH;
    int loc[CH];
    int sum = 0;
#pragma unroll
    for (int i = 0; i < CH; ++i) {
        int idx = base + i;
        int v = (idx < NNODES) ? g_cnt[idx] : 0;
        loc[i] = sum;
        sum += v;
    }
    sh[t] = sum;
    __syncthreads();
    for (int d = 1; d < 1024; d <<= 1) {
        int v = (t >= d) ? sh[t - d] : 0;
        __syncthreads();
        sh[t] += v;
        __syncthreads();
    }
    int excl = (t > 0) ? sh[t - 1] : 0;
#pragma unroll
    for (int i = 0; i < CH; ++i) {
        int idx = base + i;
        if (idx < NNODES) g_off[idx] = excl + loc[i];
    }
    if (t == 1023) g_off[NNODES] = sh[1023];
}

__global__ void fill_kernel(const int* __restrict__ src, const int* __restrict__ dst,
                            const float* __restrict__ w) {
    int e = blockIdx.x * blockDim.x + threadIdx.x;
    if (e < NE) {
        int pos = g_off[dst[e]] + g_rank[e];
        g_edges[pos] = make_int2(src[e], __float_as_int(w[e]));
    }
}

// ---------------------------------------------------------------------------
// gather1: hN[n] = (1/deg) * sum_{e: dst=n} h[src_e] * w_e      (D = 128)
// one warp per node, lane holds float4
// ---------------------------------------------------------------------------
__global__ __launch_bounds__(256)
void gather1_kernel(const float* __restrict__ h) {
    int gw = (blockIdx.x * blockDim.x + threadIdx.x) >> 5;
    if (gw >= NNODES) return;
    int lane = threadIdx.x & 31;
    int s = g_off[gw], e = g_off[gw + 1];
    float4 acc = make_float4(0.f, 0.f, 0.f, 0.f);
    int j = s;
    for (; j + 3 < e; j += 4) {
        int2 e0 = g_edges[j];
        int2 e1 = g_edges[j + 1];
        int2 e2 = g_edges[j + 2];
        int2 e3 = g_edges[j + 3];
        float4 v0 = *reinterpret_cast<const float4*>(h + (size_t)e0.x * DIN + lane * 4);
        float4 v1 = *reinterpret_cast<const float4*>(h + (size_t)e1.x * DIN + lane * 4);
        float4 v2 = *reinterpret_cast<const float4*>(h + (size_t)e2.x * DIN + lane * 4);
        float4 v3 = *reinterpret_cast<const float4*>(h + (size_t)e3.x * DIN + lane * 4);
        float w0 = __int_as_float(e0.y), w1 = __int_as_float(e1.y);
        float w2 = __int_as_float(e2.y), w3 = __int_as_float(e3.y);
        acc.x = fmaf(v0.x, w0, acc.x); acc.y = fmaf(v0.y, w0, acc.y);
        acc.z = fmaf(v0.z, w0, acc.z); acc.w = fmaf(v0.w, w0, acc.w);
        acc.x = fmaf(v1.x, w1, acc.x); acc.y = fmaf(v1.y, w1, acc.y);
        acc.z = fmaf(v1.z, w1, acc.z); acc.w = fmaf(v1.w, w1, acc.w);
        acc.x = fmaf(v2.x, w2, acc.x); acc.y = fmaf(v2.y, w2, acc.y);
        acc.z = fmaf(v2.z, w2, acc.z); acc.w = fmaf(v2.w, w2, acc.w);
        acc.x = fmaf(v3.x, w3, acc.x); acc.y = fmaf(v3.y, w3, acc.y);
        acc.z = fmaf(v3.z, w3, acc.z); acc.w = fmaf(v3.w, w3, acc.w);
    }
    for (; j < e; ++j) {
        int2 e0 = g_edges[j];
        float w0 = __int_as_float(e0.y);
        float4 v0 = *reinterpret_cast<const float4*>(h + (size_t)e0.x * DIN + lane * 4);
        acc.x = fmaf(v0.x, w0, acc.x); acc.y = fmaf(v0.y, w0, acc.y);
        acc.z = fmaf(v0.z, w0, acc.z); acc.w = fmaf(v0.w, w0, acc.w);
    }
    float inv = (e > s) ? 1.0f / (float)(e - s) : 0.0f;
    acc.x *= inv; acc.y *= inv; acc.z *= inv; acc.w *= inv;
    *reinterpret_cast<float4*>(g_hN + (size_t)gw * DIN + lane * 4) = acc;
}

// ---------------------------------------------------------------------------
// gather2: out[n] += (1/deg) * sum_{e: dst=n} y[src_e] * w_e     (D = 64)
// one warp per node, lane holds float2
// ---------------------------------------------------------------------------
__global__ __launch_bounds__(256)
void gather2_kernel(float* __restrict__ out) {
    int gw = (blockIdx.x * blockDim.x + threadIdx.x) >> 5;
    if (gw >= NNODES) return;
    int lane = threadIdx.x & 31;
    int s = g_off[gw], e = g_off[gw + 1];
    float2 acc = make_float2(0.f, 0.f);
    int j = s;
    for (; j + 3 < e; j += 4) {
        int2 e0 = g_edges[j];
        int2 e1 = g_edges[j + 1];
        int2 e2 = g_edges[j + 2];
        int2 e3 = g_edges[j + 3];
        float2 v0 = *reinterpret_cast<const float2*>(g_y + (size_t)e0.x * DOUT + lane * 2);
        float2 v1 = *reinterpret_cast<const float2*>(g_y + (size_t)e1.x * DOUT + lane * 2);
        float2 v2 = *reinterpret_cast<const float2*>(g_y + (size_t)e2.x * DOUT + lane * 2);
        float2 v3 = *reinterpret_cast<const float2*>(g_y + (size_t)e3.x * DOUT + lane * 2);
        float w0 = __int_as_float(e0.y), w1 = __int_as_float(e1.y);
        float w2 = __int_as_float(e2.y), w3 = __int_as_float(e3.y);
        acc.x = fmaf(v0.x, w0, acc.x); acc.y = fmaf(v0.y, w0, acc.y);
        acc.x = fmaf(v1.x, w1, acc.x); acc.y = fmaf(v1.y, w1, acc.y);
        acc.x = fmaf(v2.x, w2, acc.x); acc.y = fmaf(v2.y, w2, acc.y);
        acc.x = fmaf(v3.x, w3, acc.x); acc.y = fmaf(v3.y, w3, acc.y);
    }
    for (; j < e; ++j) {
        int2 e0 = g_edges[j];
        float w0 = __int_as_float(e0.y);
        float2 v0 = *reinterpret_cast<const float2*>(g_y + (size_t)e0.x * DOUT + lane * 2);
        acc.x = fmaf(v0.x, w0, acc.x); acc.y = fmaf(v0.y, w0, acc.y);
    }
    float inv = (e > s) ? 1.0f / (float)(e - s) : 0.0f;
    float2* op = reinterpret_cast<float2*>(out + (size_t)gw * DOUT + lane * 2);
    float2 cur = *op;
    cur.x = fmaf(acc.x, inv, cur.x);
    cur.y = fmaf(acc.y, inv, cur.y);
    *op = cur;
}

// ---------------------------------------------------------------------------
// gemm1: x = relu( [h | hN] @ W1 + b1 )   M=10000, K=256, N=256
// BM=128, BN=64, BK=16, 128 threads, 8x8 microtile
// ---------------------------------------------------------------------------
__global__ __launch_bounds__(128)
void gemm1_kernel(const float* __restrict__ A1, const float* __restrict__ A2,
                  const float* __restrict__ W, const float* __restrict__ bias,
                  float* __restrict__ C) {
    constexpr int BM = 128, BN = 64, BK = 16, K = 256, K1 = 128, NT = 256;
    __shared__ float As[BK][BM];
    __shared__ float Bs[BK][BN];

    int tid  = threadIdx.x;
    int row0 = blockIdx.x * BM;
    int col0 = blockIdx.y * BN;

    int a_m  = row0 + tid;                 // one A row per thread
    bool a_ok = (a_m < NNODES);

    int b_r = tid >> 3;                    // 0..15
    int b_c = (tid & 7) * 8;               // 0..56 (two float4)

    int ty = tid >> 3, tx = tid & 7;       // 16 x 8
    int cm = ty * 8, cn = tx * 8;

    float acc[8][8] = {};

    for (int kb = 0; kb < K; kb += BK) {
        const float* Ab = (kb < K1) ? A1 : A2;
        int kloc = (kb < K1) ? kb : kb - K1;
        const float* arow = Ab + (size_t)a_m * K1 + kloc;
#pragma unroll
        for (int q = 0; q < 4; ++q) {
            float4 av = make_float4(0.f, 0.f, 0.f, 0.f);
            if (a_ok) av = *reinterpret_cast<const float4*>(arow + q * 4);
            As[q * 4 + 0][tid] = av.x;
            As[q * 4 + 1][tid] = av.y;
            As[q * 4 + 2][tid] = av.z;
            As[q * 4 + 3][tid] = av.w;
        }
        {
            const float* wrow = W + (size_t)(kb + b_r) * NT + col0 + b_c;
            *reinterpret_cast<float4*>(&Bs[b_r][b_c])     = *reinterpret_cast<const float4*>(wrow);
            *reinterpret_cast<float4*>(&Bs[b_r][b_c + 4]) = *reinterpret_cast<const float4*>(wrow + 4);
        }
        __syncthreads();
#pragma unroll
        for (int kk = 0; kk < BK; ++kk) {
            float a[8], b[8];
            *reinterpret_cast<float4*>(a)     = *reinterpret_cast<const float4*>(&As[kk][cm]);
            *reinterpret_cast<float4*>(a + 4) = *reinterpret_cast<const float4*>(&As[kk][cm + 4]);
            *reinterpret_cast<float4*>(b)     = *reinterpret_cast<const float4*>(&Bs[kk][cn]);
            *reinterpret_cast<float4*>(b + 4) = *reinterpret_cast<const float4*>(&Bs[kk][cn + 4]);
#pragma unroll
            for (int i = 0; i < 8; ++i)
#pragma unroll
                for (int jj = 0; jj < 8; ++jj)
                    acc[i][jj] = fmaf(a[i], b[jj], acc[i][jj]);
        }
        __syncthreads();
    }

#pragma unroll
    for (int i = 0; i < 8; ++i) {
        int m = row0 + cm + i;
        if (m < NNODES) {
#pragma unroll
            for (int j0 = 0; j0 < 8; j0 += 4) {
                float4 o;
                o.x = fmaxf(acc[i][j0 + 0] + bias[col0 + cn + j0 + 0], 0.f);
                o.y = fmaxf(acc[i][j0 + 1] + bias[col0 + cn + j0 + 1], 0.f);
                o.z = fmaxf(acc[i][j0 + 2] + bias[col0 + cn + j0 + 2], 0.f);
                o.w = fmaxf(acc[i][j0 + 3] + bias[col0 + cn + j0 + 3], 0.f);
                *reinterpret_cast<float4*>(C + (size_t)m * NT + col0 + cn + j0) = o;
            }
        }
    }
}

// ---------------------------------------------------------------------------
// gemm2 (merged): C' = x @ [W2_top | W2_bot]   M=10000, K=256, N=128
//   cols 0..63  -> out (+ b2)
//   cols 64..127-> g_y
// BM=64, BN=128, BK=16, 128 threads, 8x8 microtile
// ---------------------------------------------------------------------------
__global__ __launch_bounds__(128)
void gemm2_kernel(const float* __restrict__ A, const float* __restrict__ W2,
                  const float* __restrict__ bias, float* __restrict__ out,
                  float* __restrict__ Y) {
    constexpr int BM = 64, BN = 128, BK = 16, K = 256, KA = 256;
    __shared__ float As[BK][BM];
    __shared__ float Bs[BK][BN];

    int tid  = threadIdx.x;
    int row0 = blockIdx.x * BM;

    int a_row = tid >> 1;                  // 0..63
    int a_k8  = (tid & 1) * 8;             // 0 or 8
    int a_m   = row0 + a_row;
    bool a_ok = (a_m < NNODES);

    int b_r  = tid >> 3;                   // 0..15
    int b_c  = (tid & 7) * 16;             // 0..112 (four float4)

    int ty = tid >> 4, tx = tid & 15;      // 8 x 16
    int cm = ty * 8, cn = tx * 8;

    float acc[8][8] = {};

    for (int kb = 0; kb < K; kb += BK) {
        {
            const float* arow = A + (size_t)a_m * KA + kb + a_k8;
#pragma unroll
            for (int q = 0; q < 2; ++q) {
                float4 av = make_float4(0.f, 0.f, 0.f, 0.f);
                if (a_ok) av = *reinterpret_cast<const float4*>(arow + q * 4);
                As[a_k8 + q * 4 + 0][a_row] = av.x;
                As[a_k8 + q * 4 + 1][a_row] = av.y;
                As[a_k8 + q * 4 + 2][a_row] = av.z;
                As[a_k8 + q * 4 + 3][a_row] = av.w;
            }
        }
        {
            // B' columns: c<64 from W2 rows [kb..], c>=64 from W2 rows [kb+256..]
#pragma unroll
            for (int q = 0; q < 4; ++q) {
                int c = b_c + q * 4;
                int wrow = (c < 64) ? (kb + b_r) : (kb + b_r + 256);
                int wcol = (c < 64) ? c : (c - 64);
                *reinterpret_cast<float4*>(&Bs[b_r][c]) =
                    *reinterpret_cast<const float4*>(W2 + (size_t)wrow * DOUT + wcol);
            }
        }
        __syncthreads();
#pragma unroll
        for (int kk = 0; kk < BK; ++kk) {
            float a[8], b[8];
            *reinterpret_cast<float4*>(a)     = *reinterpret_cast<const float4*>(&As[kk][cm]);
            *reinterpret_cast<float4*>(a + 4) = *reinterpret_cast<const float4*>(&As[kk][cm + 4]);
            *reinterpret_cast<float4*>(b)     = *reinterpret_cast<const float4*>(&Bs[kk][cn]);
            *reinterpret_cast<float4*>(b + 4) = *reinterpret_cast<const float4*>(&Bs[kk][cn + 4]);
#pragma unroll
            for (int i = 0; i < 8; ++i)
#pragma unroll
                for (int jj = 0; jj < 8; ++jj)
                    acc[i][jj] = fmaf(a[i], b[jj], acc[i][jj]);
        }
        __syncthreads();
    }

    bool top = (cn < 64);   // this thread's 8 cols are entirely in one half
#pragma unroll
    for (int i = 0; i < 8; ++i) {
        int m = row0 + cm + i;
        if (m < NNODES) {
#pragma unroll
            for (int j0 = 0; j0 < 8; j0 += 4) {
                float4 o;
                if (top) {
                    int c = cn + j0;
                    o.x = acc[i][j0 + 0] + bias[c + 0];
                    o.y = acc[i][j0 + 1] + bias[c + 1];
                    o.z = acc[i][j0 + 2] + bias[c + 2];
                    o.w = acc[i][j0 + 3] + bias[c + 3];
                    *reinterpret_cast<float4*>(out + (size_t)m * DOUT + c) = o;
                } else {
                    int c = cn - 64 + j0;
                    o.x = acc[i][j0 + 0];
                    o.y = acc[i][j0 + 1];
                    o.z = acc[i][j0 + 2];
                    o.w = acc[i][j0 + 3];
                    *reinterpret_cast<float4*>(Y + (size_t)m * DOUT + c) = o;
                }
            }
        }
    }
}

// ---------------------------------------------------------------------------
extern "C" void kernel_launch(void* const* d_in, const int* in_sizes, int n_in,
                              void* d_out, int out_size) {
    const float* h   = (const float*)d_in[0];
    const float* w   = (const float*)d_in[1];
    const int*   src = (const int*)  d_in[2];
    const int*   dst = (const int*)  d_in[3];
    const float* W1  = (const float*)d_in[4];
    const float* b1  = (const float*)d_in[5];
    const float* W2  = (const float*)d_in[6];
    const float* b2  = (const float*)d_in[7];
    float* out = (float*)d_out;

    float *hN, *x, *y;
    cudaGetSymbolAddress((void**)&hN, g_hN);
    cudaGetSymbolAddress((void**)&x,  g_x);
    cudaGetSymbolAddress((void**)&y,  g_y);

    // CSR build (by dst)
    zero_cnt_kernel<<<(NNODES + 255) / 256, 256>>>();
    count_rank_kernel<<<(NE + 255) / 256, 256>>>(dst);
    scan_kernel<<<1, 1024>>>();
    fill_kernel<<<(NE + 255) / 256, 256>>>(src, dst, w);

    // layer 1: gather (mean, normalized) then GEMM+relu
    gather1_kernel<<<(NNODES * 32 + 255) / 256, 256>>>(h);
    dim3 g1((NNODES + 127) / 128, DHID / 64);
    gemm1_kernel<<<g1, 128>>>(h, hN, W1, b1, x);

    // layer 2 via linearity: [out | y] = x @ [W2_top | W2_bot] ; out += agg(y)
    gemm2_kernel<<<(NNODES + 63) / 64, 128>>>(x, W2, b2, out, y);
    gather2_kernel<<<(NNODES * 32 + 255) / 256, 256>>>(out);
}

// round 6
// speedup vs baseline: 1.6351x; 1.6351x over previous
#include <cuda_runtime.h>

static constexpr int NNODES = 10000;
static constexpr int NE     = 640000;
static constexpr int DIN    = 128;
static constexpr int DHID   = 256;
static constexpr int DOUT   = 64;

// ---- scratch (__device__ globals: allocation-free rule) ----
__device__ int   g_cnt[NNODES];
__device__ int   g_off[NNODES + 1];
__device__ int   g_rank[NE];
__device__ int2  g_edges[NE];            // (src, w bits) grouped by dst
__device__ float g_hN[NNODES * DIN];     // layer-1 mean aggregate (normalized)
__device__ float g_x [NNODES * DHID];    // layer-1 output (post relu)
__device__ float g_y [NNODES * DOUT];    // x @ W2_bot

// ---------------------------------------------------------------------------
// CSR build: zero -> count(+rank) -> scan -> fill(no atomics)
// ---------------------------------------------------------------------------
__global__ void zero_cnt_kernel() {
    int i = blockIdx.x * blockDim.x + threadIdx.x;
    if (i < NNODES) g_cnt[i] = 0;
}

__global__ void count_rank_kernel(const int* __restrict__ dst) {
    int e = blockIdx.x * blockDim.x + threadIdx.x;
    if (e < NE) g_rank[e] = atomicAdd(&g_cnt[dst[e]], 1);
}

__global__ void scan_kernel() {
    __shared__ int sh[1024];
    constexpr int CH = 10;                // 1024*10 >= 10000
    int t = threadIdx.x;
    int base = t * CH;
    int loc[CH];
    int sum = 0;
#pragma unroll
    for (int i = 0; i < CH; ++i) {
        int idx = base + i;
        int v = (idx < NNODES) ? g_cnt[idx] : 0;
        loc[i] = sum;
        sum += v;
    }
    sh[t] = sum;
    __syncthreads();
    for (int d = 1; d < 1024; d <<= 1) {
        int v = (t >= d) ? sh[t - d] : 0;
        __syncthreads();
        sh[t] += v;
        __syncthreads();
    }
    int excl = (t > 0) ? sh[t - 1] : 0;
#pragma unroll
    for (int i = 0; i < CH; ++i) {
        int idx = base + i;
        if (idx < NNODES) g_off[idx] = excl + loc[i];
    }
    if (t == 1023) g_off[NNODES] = sh[1023];
}

__global__ void fill_kernel(const int* __restrict__ src, const int* __restrict__ dst,
                            const float* __restrict__ w) {
    int e = blockIdx.x * blockDim.x + threadIdx.x;
    if (e < NE) {
        int pos = g_off[dst[e]] + g_rank[e];
        g_edges[pos] = make_int2(src[e], __float_as_int(w[e]));
    }
}

// ---------------------------------------------------------------------------
// gather1: hN[n] = (1/deg) * sum_{e: dst=n} h[src_e] * w_e      (D = 128)
// one warp per node, lane holds float4
// ---------------------------------------------------------------------------
__global__ __launch_bounds__(256)
void gather1_kernel(const float* __restrict__ h) {
    int gw = (blockIdx.x * blockDim.x + threadIdx.x) >> 5;
    if (gw >= NNODES) return;
    int lane = threadIdx.x & 31;
    int s = g_off[gw], e = g_off[gw + 1];
    float4 acc = make_float4(0.f, 0.f, 0.f, 0.f);
    int j = s;
    for (; j + 3 < e; j += 4) {
        int2 e0 = g_edges[j];
        int2 e1 = g_edges[j + 1];
        int2 e2 = g_edges[j + 2];
        int2 e3 = g_edges[j + 3];
        float4 v0 = *reinterpret_cast<const float4*>(h + (size_t)e0.x * DIN + lane * 4);
        float4 v1 = *reinterpret_cast<const float4*>(h + (size_t)e1.x * DIN + lane * 4);
        float4 v2 = *reinterpret_cast<const float4*>(h + (size_t)e2.x * DIN + lane * 4);
        float4 v3 = *reinterpret_cast<const float4*>(h + (size_t)e3.x * DIN + lane * 4);
        float w0 = __int_as_float(e0.y), w1 = __int_as_float(e1.y);
        float w2 = __int_as_float(e2.y), w3 = __int_as_float(e3.y);
        acc.x = fmaf(v0.x, w0, acc.x); acc.y = fmaf(v0.y, w0, acc.y);
        acc.z = fmaf(v0.z, w0, acc.z); acc.w = fmaf(v0.w, w0, acc.w);
        acc.x = fmaf(v1.x, w1, acc.x); acc.y = fmaf(v1.y, w1, acc.y);
        acc.z = fmaf(v1.z, w1, acc.z); acc.w = fmaf(v1.w, w1, acc.w);
        acc.x = fmaf(v2.x, w2, acc.x); acc.y = fmaf(v2.y, w2, acc.y);
        acc.z = fmaf(v2.z, w2, acc.z); acc.w = fmaf(v2.w, w2, acc.w);
        acc.x = fmaf(v3.x, w3, acc.x); acc.y = fmaf(v3.y, w3, acc.y);
        acc.z = fmaf(v3.z, w3, acc.z); acc.w = fmaf(v3.w, w3, acc.w);
    }
    for (; j < e; ++j) {
        int2 e0 = g_edges[j];
        float w0 = __int_as_float(e0.y);
        float4 v0 = *reinterpret_cast<const float4*>(h + (size_t)e0.x * DIN + lane * 4);
        acc.x = fmaf(v0.x, w0, acc.x); acc.y = fmaf(v0.y, w0, acc.y);
        acc.z = fmaf(v0.z, w0, acc.z); acc.w = fmaf(v0.w, w0, acc.w);
    }
    float inv = (e > s) ? 1.0f / (float)(e - s) : 0.0f;
    acc.x *= inv; acc.y *= inv; acc.z *= inv; acc.w *= inv;
    *reinterpret_cast<float4*>(g_hN + (size_t)gw * DIN + lane * 4) = acc;
}

// ---------------------------------------------------------------------------
// gather2: out[n] += (1/deg) * sum_{e: dst=n} y[src_e] * w_e     (D = 64)
// one warp per node, lane holds float2
// ---------------------------------------------------------------------------
__global__ __launch_bounds__(256)
void gather2_kernel(float* __restrict__ out) {
    int gw = (blockIdx.x * blockDim.x + threadIdx.x) >> 5;
    if (gw >= NNODES) return;
    int lane = threadIdx.x & 31;
    int s = g_off[gw], e = g_off[gw + 1];
    float2 acc = make_float2(0.f, 0.f);
    int j = s;
    for (; j + 3 < e; j += 4) {
        int2 e0 = g_edges[j];
        int2 e1 = g_edges[j + 1];
        int2 e2 = g_edges[j + 2];
        int2 e3 = g_edges[j + 3];
        float2 v0 = *reinterpret_cast<const float2*>(g_y + (size_t)e0.x * DOUT + lane * 2);
        float2 v1 = *reinterpret_cast<const float2*>(g_y + (size_t)e1.x * DOUT + lane * 2);
        float2 v2 = *reinterpret_cast<const float2*>(g_y + (size_t)e2.x * DOUT + lane * 2);
        float2 v3 = *reinterpret_cast<const float2*>(g_y + (size_t)e3.x * DOUT + lane * 2);
        float w0 = __int_as_float(e0.y), w1 = __int_as_float(e1.y);
        float w2 = __int_as_float(e2.y), w3 = __int_as_float(e3.y);
        acc.x = fmaf(v0.x, w0, acc.x); acc.y = fmaf(v0.y, w0, acc.y);
        acc.x = fmaf(v1.x, w1, acc.x); acc.y = fmaf(v1.y, w1, acc.y);
        acc.x = fmaf(v2.x, w2, acc.x); acc.y = fmaf(v2.y, w2, acc.y);
        acc.x = fmaf(v3.x, w3, acc.x); acc.y = fmaf(v3.y, w3, acc.y);
    }
    for (; j < e; ++j) {
        int2 e0 = g_edges[j];
        float w0 = __int_as_float(e0.y);
        float2 v0 = *reinterpret_cast<const float2*>(g_y + (size_t)e0.x * DOUT + lane * 2);
        acc.x = fmaf(v0.x, w0, acc.x); acc.y = fmaf(v0.y, w0, acc.y);
    }
    float inv = (e > s) ? 1.0f / (float)(e - s) : 0.0f;
    float2* op = reinterpret_cast<float2*>(out + (size_t)gw * DOUT + lane * 2);
    float2 cur = *op;
    cur.x = fmaf(acc.x, inv, cur.x);
    cur.y = fmaf(acc.y, inv, cur.y);
    *op = cur;
}

// ---------------------------------------------------------------------------
// gemm1: x = relu( [h | hN] @ W1 + b1 )   M=10000, K=256, N=256
// BM=BN=64, BK=16, 64 threads, 8x8 microtile   (known-good R2 config)
// ---------------------------------------------------------------------------
__global__ __launch_bounds__(64)
void gemm1_kernel(const float* __restrict__ A1, const float* __restrict__ A2,
                  const float* __restrict__ W, const float* __restrict__ bias,
                  float* __restrict__ C) {
    constexpr int BM = 64, BN = 64, BK = 16, K = 256, K1 = 128, NT = 256;
    __shared__ float As[BK][BM];
    __shared__ float Bs[BK][BN];

    int tid  = threadIdx.x;
    int row0 = blockIdx.x * BM;
    int col0 = blockIdx.y * BN;

    int a_m  = row0 + tid;
    bool a_ok = (a_m < NNODES);

    int b_r0 = tid >> 4;           // 0..3
    int b_c4 = (tid & 15) * 4;     // 0..60

    int ty = tid >> 3, tx = tid & 7;
    int cm = ty * 8, cn = tx * 8;

    float acc[8][8] = {};

    for (int kb = 0; kb < K; kb += BK) {
        const float* Ab = (kb < K1) ? A1 : A2;
        int kloc = (kb < K1) ? kb : kb - K1;
        const float* arow = Ab + (size_t)a_m * K1 + kloc;
#pragma unroll
        for (int q = 0; q < 4; ++q) {
            float4 av = make_float4(0.f, 0.f, 0.f, 0.f);
            if (a_ok) av = *reinterpret_cast<const float4*>(arow + q * 4);
            As[q * 4 + 0][tid] = av.x;
            As[q * 4 + 1][tid] = av.y;
            As[q * 4 + 2][tid] = av.z;
            As[q * 4 + 3][tid] = av.w;
        }
#pragma unroll
        for (int q = 0; q < 4; ++q) {
            int kr = b_r0 + q * 4;  // 0..15
            *reinterpret_cast<float4*>(&Bs[kr][b_c4]) =
                *reinterpret_cast<const float4*>(W + (size_t)(kb + kr) * NT + col0 + b_c4);
        }
        __syncthreads();
#pragma unroll
        for (int kk = 0; kk < BK; ++kk) {
            float a[8], b[8];
            *reinterpret_cast<float4*>(a)     = *reinterpret_cast<const float4*>(&As[kk][cm]);
            *reinterpret_cast<float4*>(a + 4) = *reinterpret_cast<const float4*>(&As[kk][cm + 4]);
            *reinterpret_cast<float4*>(b)     = *reinterpret_cast<const float4*>(&Bs[kk][cn]);
            *reinterpret_cast<float4*>(b + 4) = *reinterpret_cast<const float4*>(&Bs[kk][cn + 4]);
#pragma unroll
            for (int i = 0; i < 8; ++i)
#pragma unroll
                for (int jj = 0; jj < 8; ++jj)
                    acc[i][jj] = fmaf(a[i], b[jj], acc[i][jj]);
        }
        __syncthreads();
    }

#pragma unroll
    for (int i = 0; i < 8; ++i) {
        int m = row0 + cm + i;
        if (m < NNODES) {
#pragma unroll
            for (int j0 = 0; j0 < 8; j0 += 4) {
                float4 o;
                o.x = fmaxf(acc[i][j0 + 0] + bias[col0 + cn + j0 + 0], 0.f);
                o.y = fmaxf(acc[i][j0 + 1] + bias[col0 + cn + j0 + 1], 0.f);
                o.z = fmaxf(acc[i][j0 + 2] + bias[col0 + cn + j0 + 2], 0.f);
                o.w = fmaxf(acc[i][j0 + 3] + bias[col0 + cn + j0 + 3], 0.f);
                *reinterpret_cast<float4*>(C + (size_t)m * NT + col0 + cn + j0) = o;
            }
        }
    }
}

// ---------------------------------------------------------------------------
// gemm2: blockIdx.y==0: out = x @ W2[0:256]   + b2   (written to d_out)
//        blockIdx.y==1: y   = x @ W2[256:512]        (written to g_y)
// M=10000, K=256, N=64 each.  BM=BN=64, BK=16, 64 threads, 8x8 microtile
// (known-good R2 config)
// ---------------------------------------------------------------------------
__global__ __launch_bounds__(64)
void gemm2_kernel(const float* __restrict__ A, const float* __restrict__ W2,
                  const float* __restrict__ bias, float* __restrict__ out,
                  float* __restrict__ Y) {
    constexpr int BM = 64, BN = 64, BK = 16, K = 256, KA = 256;
    __shared__ float As[BK][BM];
    __shared__ float Bs[BK][BN];

    int tid  = threadIdx.x;
    int row0 = blockIdx.x * BM;
    bool top = (blockIdx.y == 0);
    const float* W = top ? W2 : (W2 + (size_t)256 * DOUT);

    int a_m  = row0 + tid;
    bool a_ok = (a_m < NNODES);

    int b_r0 = tid >> 4;
    int b_c4 = (tid & 15) * 4;

    int ty = tid >> 3, tx = tid & 7;
    int cm = ty * 8, cn = tx * 8;

    float acc[8][8] = {};

    for (int kb = 0; kb < K; kb += BK) {
        const float* arow = A + (size_t)a_m * KA + kb;
#pragma unroll
        for (int q = 0; q < 4; ++q) {
            float4 av = make_float4(0.f, 0.f, 0.f, 0.f);
            if (a_ok) av = *reinterpret_cast<const float4*>(arow + q * 4);
            As[q * 4 + 0][tid] = av.x;
            As[q * 4 + 1][tid] = av.y;
            As[q * 4 + 2][tid] = av.z;
            As[q * 4 + 3][tid] = av.w;
        }
#pragma unroll
        for (int q = 0; q < 4; ++q) {
            int kr = b_r0 + q * 4;
            *reinterpret_cast<float4*>(&Bs[kr][b_c4]) =
                *reinterpret_cast<const float4*>(W + (size_t)(kb + kr) * DOUT + b_c4);
        }
        __syncthreads();
#pragma unroll
        for (int kk = 0; kk < BK; ++kk) {
            float a[8], b[8];
            *reinterpret_cast<float4*>(a)     = *reinterpret_cast<const float4*>(&As[kk][cm]);
            *reinterpret_cast<float4*>(a + 4) = *reinterpret_cast<const float4*>(&As[kk][cm + 4]);
            *reinterpret_cast<float4*>(b)     = *reinterpret_cast<const float4*>(&Bs[kk][cn]);
            *reinterpret_cast<float4*>(b + 4) = *reinterpret_cast<const float4*>(&Bs[kk][cn + 4]);
#pragma unroll
            for (int i = 0; i < 8; ++i)
#pragma unroll
                for (int jj = 0; jj < 8; ++jj)
                    acc[i][jj] = fmaf(a[i], b[jj], acc[i][jj]);
        }
        __syncthreads();
    }

#pragma unroll
    for (int i = 0; i < 8; ++i) {
        int m = row0 + cm + i;
        if (m < NNODES) {
#pragma unroll
            for (int j0 = 0; j0 < 8; j0 += 4) {
                float4 o;
                if (top) {
                    o.x = acc[i][j0 + 0] + bias[cn + j0 + 0];
                    o.y = acc[i][j0 + 1] + bias[cn + j0 + 1];
                    o.z = acc[i][j0 + 2] + bias[cn + j0 + 2];
                    o.w = acc[i][j0 + 3] + bias[cn + j0 + 3];
                    *reinterpret_cast<float4*>(out + (size_t)m * DOUT + cn + j0) = o;
                } else {
                    o.x = acc[i][j0 + 0];
                    o.y = acc[i][j0 + 1];
                    o.z = acc[i][j0 + 2];
                    o.w = acc[i][j0 + 3];
                    *reinterpret_cast<float4*>(Y + (size_t)m * DOUT + cn + j0) = o;
                }
            }
        }
    }
}

// ---------------------------------------------------------------------------
extern "C" void kernel_launch(void* const* d_in, const int* in_sizes, int n_in,
                              void* d_out, int out_size) {
    const float* h   = (const float*)d_in[0];
    const float* w   = (const float*)d_in[1];
    const int*   src = (const int*)  d_in[2];
    const int*   dst = (const int*)  d_in[3];
    const float* W1  = (const float*)d_in[4];
    const float* b1  = (const float*)d_in[5];
    const float* W2  = (const float*)d_in[6];
    const float* b2  = (const float*)d_in[7];
    float* out = (float*)d_out;

    float *hN, *x, *y;
    cudaGetSymbolAddress((void**)&hN, g_hN);
    cudaGetSymbolAddress((void**)&x,  g_x);
    cudaGetSymbolAddress((void**)&y,  g_y);

    // CSR build (by dst)
    zero_cnt_kernel<<<(NNODES + 255) / 256, 256>>>();
    count_rank_kernel<<<(NE + 255) / 256, 256>>>(dst);
    scan_kernel<<<1, 1024>>>();
    fill_kernel<<<(NE + 255) / 256, 256>>>(src, dst, w);

    // layer 1: gather (mean, normalized) then GEMM+relu
    gather1_kernel<<<(NNODES * 32 + 255) / 256, 256>>>(h);
    dim3 g1((NNODES + 63) / 64, DHID / 64);
    gemm1_kernel<<<g1, 64>>>(h, hN, W1, b1, x);

    // layer 2 via linearity: out = x@W2_top + b2 ; y = x@W2_bot ; out += agg(y)
    dim3 g2((NNODES + 63) / 64, 2);
    gemm2_kernel<<<g2, 64>>>(x, W2, b2, out, y);
    gather2_kernel<<<(NNODES * 32 + 255) / 256, 256>>>(out);
}

// round 7
// speedup vs baseline: 1.7576x; 1.0749x over previous
#include <cuda_runtime.h>
#include <cuda_fp16.h>

static constexpr int NNODES = 10000;
static constexpr int NE     = 640000;
static constexpr int DIN    = 128;
static constexpr int DHID   = 256;
static constexpr int DOUT   = 64;

// ---- scratch (__device__ globals: allocation-free rule) ----
__device__ int    g_cnt[NNODES];
__device__ int    g_off[NNODES + 1];
__device__ int    g_rank[NE];
__device__ int2   g_edges[NE];            // (src, w bits) grouped by dst
__device__ __half g_hh[NNODES * DIN];     // h in fp16 (gather operand)
__device__ float  g_hN[NNODES * DIN];     // layer-1 mean aggregate (normalized)
__device__ float  g_x [NNODES * DHID];    // layer-1 output (post relu)
__device__ __half g_yh[NNODES * DOUT];    // x @ W2_bot in fp16 (gather operand)

// ---------------------------------------------------------------------------
// CSR build: zero -> count(+rank) -> scan -> fill(no atomics)
// ---------------------------------------------------------------------------
__global__ void zero_cnt_kernel() {
    int i = blockIdx.x * blockDim.x + threadIdx.x;
    if (i < NNODES) g_cnt[i] = 0;
}

__global__ void count_rank_kernel(const int* __restrict__ dst) {
    int e = blockIdx.x * blockDim.x + threadIdx.x;
    if (e < NE) g_rank[e] = atomicAdd(&g_cnt[dst[e]], 1);
}

__global__ void scan_kernel() {
    __shared__ int sh[1024];
    constexpr int CH = 10;                // 1024*10 >= 10000
    int t = threadIdx.x;
    int base = t * CH;
    int loc[CH];
    int sum = 0;
#pragma unroll
    for (int i = 0; i < CH; ++i) {
        int idx = base + i;
        int v = (idx < NNODES) ? g_cnt[idx] : 0;
        loc[i] = sum;
        sum += v;
    }
    sh[t] = sum;
    __syncthreads();
    for (int d = 1; d < 1024; d <<= 1) {
        int v = (t >= d) ? sh[t - d] : 0;
        __syncthreads();
        sh[t] += v;
        __syncthreads();
    }
    int excl = (t > 0) ? sh[t - 1] : 0;
#pragma unroll
    for (int i = 0; i < CH; ++i) {
        int idx = base + i;
        if (idx < NNODES) g_off[idx] = excl + loc[i];
    }
    if (t == 1023) g_off[NNODES] = sh[1023];
}

__global__ void fill_kernel(const int* __restrict__ src, const int* __restrict__ dst,
                            const float* __restrict__ w) {
    int e = blockIdx.x * blockDim.x + threadIdx.x;
    if (e < NE) {
        int pos = g_off[dst[e]] + g_rank[e];
        g_edges[pos] = make_int2(src[e], __float_as_int(w[e]));
    }
}

// ---------------------------------------------------------------------------
// convert h (fp32) -> g_hh (fp16)
// ---------------------------------------------------------------------------
__global__ void convert_h_kernel(const float* __restrict__ h) {
    int i = blockIdx.x * blockDim.x + threadIdx.x;
    if (i < NNODES * DIN / 2) {
        float2 v = reinterpret_cast<const float2*>(h)[i];
        reinterpret_cast<__half2*>(g_hh)[i] = __floats2half2_rn(v.x, v.y);
    }
}

// ---------------------------------------------------------------------------
// gather1: hN[n] = (1/deg) * sum_{e: dst=n} h[src_e] * w_e      (D = 128, fp16 reads)
// one warp per node; lane covers 4 halves (8B load)
// ---------------------------------------------------------------------------
__global__ __launch_bounds__(256)
void gather1_kernel() {
    int gw = (blockIdx.x * blockDim.x + threadIdx.x) >> 5;
    if (gw >= NNODES) return;
    int lane = threadIdx.x & 31;
    int s = g_off[gw], e = g_off[gw + 1];
    float4 acc = make_float4(0.f, 0.f, 0.f, 0.f);
    int j = s;
    for (; j + 3 < e; j += 4) {
        int2 e0 = g_edges[j];
        int2 e1 = g_edges[j + 1];
        int2 e2 = g_edges[j + 2];
        int2 e3 = g_edges[j + 3];
        uint2 r0 = *reinterpret_cast<const uint2*>(g_hh + (size_t)e0.x * DIN + lane * 4);
        uint2 r1 = *reinterpret_cast<const uint2*>(g_hh + (size_t)e1.x * DIN + lane * 4);
        uint2 r2 = *reinterpret_cast<const uint2*>(g_hh + (size_t)e2.x * DIN + lane * 4);
        uint2 r3 = *reinterpret_cast<const uint2*>(g_hh + (size_t)e3.x * DIN + lane * 4);
        float w0 = __int_as_float(e0.y), w1 = __int_as_float(e1.y);
        float w2 = __int_as_float(e2.y), w3 = __int_as_float(e3.y);
        {
            float2 a = __half22float2(*reinterpret_cast<__half2*>(&r0.x));
            float2 b = __half22float2(*reinterpret_cast<__half2*>(&r0.y));
            acc.x = fmaf(a.x, w0, acc.x); acc.y = fmaf(a.y, w0, acc.y);
            acc.z = fmaf(b.x, w0, acc.z); acc.w = fmaf(b.y, w0, acc.w);
        }
        {
            float2 a = __half22float2(*reinterpret_cast<__half2*>(&r1.x));
            float2 b = __half22float2(*reinterpret_cast<__half2*>(&r1.y));
            acc.x = fmaf(a.x, w1, acc.x); acc.y = fmaf(a.y, w1, acc.y);
            acc.z = fmaf(b.x, w1, acc.z); acc.w = fmaf(b.y, w1, acc.w);
        }
        {
            float2 a = __half22float2(*reinterpret_cast<__half2*>(&r2.x));
            float2 b = __half22float2(*reinterpret_cast<__half2*>(&r2.y));
            acc.x = fmaf(a.x, w2, acc.x); acc.y = fmaf(a.y, w2, acc.y);
            acc.z = fmaf(b.x, w2, acc.z); acc.w = fmaf(b.y, w2, acc.w);
        }
        {
            float2 a = __half22float2(*reinterpret_cast<__half2*>(&r3.x));
            float2 b = __half22float2(*reinterpret_cast<__half2*>(&r3.y));
            acc.x = fmaf(a.x, w3, acc.x); acc.y = fmaf(a.y, w3, acc.y);
            acc.z = fmaf(b.x, w3, acc.z); acc.w = fmaf(b.y, w3, acc.w);
        }
    }
    for (; j < e; ++j) {
        int2 e0 = g_edges[j];
        float w0 = __int_as_float(e0.y);
        uint2 r0 = *reinterpret_cast<const uint2*>(g_hh + (size_t)e0.x * DIN + lane * 4);
        float2 a = __half22float2(*reinterpret_cast<__half2*>(&r0.x));
        float2 b = __half22float2(*reinterpret_cast<__half2*>(&r0.y));
        acc.x = fmaf(a.x, w0, acc.x); acc.y = fmaf(a.y, w0, acc.y);
        acc.z = fmaf(b.x, w0, acc.z); acc.w = fmaf(b.y, w0, acc.w);
    }
    float inv = (e > s) ? 1.0f / (float)(e - s) : 0.0f;
    acc.x *= inv; acc.y *= inv; acc.z *= inv; acc.w *= inv;
    *reinterpret_cast<float4*>(g_hN + (size_t)gw * DIN + lane * 4) = acc;
}

// ---------------------------------------------------------------------------
// gather2: out[n] += (1/deg) * sum_{e: dst=n} y[src_e] * w_e     (D = 64, fp16 reads)
// one warp per node; lane covers 2 halves (4B load)
// ---------------------------------------------------------------------------
__global__ __launch_bounds__(256)
void gather2_kernel(float* __restrict__ out) {
    int gw = (blockIdx.x * blockDim.x + threadIdx.x) >> 5;
    if (gw >= NNODES) return;
    int lane = threadIdx.x & 31;
    int s = g_off[gw], e = g_off[gw + 1];
    float2 acc = make_float2(0.f, 0.f);
    int j = s;
    for (; j + 3 < e; j += 4) {
        int2 e0 = g_edges[j];
        int2 e1 = g_edges[j + 1];
        int2 e2 = g_edges[j + 2];
        int2 e3 = g_edges[j + 3];
        __half2 p0 = *reinterpret_cast<const __half2*>(g_yh + (size_t)e0.x * DOUT + lane * 2);
        __half2 p1 = *reinterpret_cast<const __half2*>(g_yh + (size_t)e1.x * DOUT + lane * 2);
        __half2 p2 = *reinterpret_cast<const __half2*>(g_yh + (size_t)e2.x * DOUT + lane * 2);
        __half2 p3 = *reinterpret_cast<const __half2*>(g_yh + (size_t)e3.x * DOUT + lane * 2);
        float w0 = __int_as_float(e0.y), w1 = __int_as_float(e1.y);
        float w2 = __int_as_float(e2.y), w3 = __int_as_float(e3.y);
        float2 v0 = __half22float2(p0), v1 = __half22float2(p1);
        float2 v2 = __half22float2(p2), v3 = __half22float2(p3);
        acc.x = fmaf(v0.x, w0, acc.x); acc.y = fmaf(v0.y, w0, acc.y);
        acc.x = fmaf(v1.x, w1, acc.x); acc.y = fmaf(v1.y, w1, acc.y);
        acc.x = fmaf(v2.x, w2, acc.x); acc.y = fmaf(v2.y, w2, acc.y);
        acc.x = fmaf(v3.x, w3, acc.x); acc.y = fmaf(v3.y, w3, acc.y);
    }
    for (; j < e; ++j) {
        int2 e0 = g_edges[j];
        float w0 = __int_as_float(e0.y);
        float2 v0 = __half22float2(*reinterpret_cast<const __half2*>(g_yh + (size_t)e0.x * DOUT + lane * 2));
        acc.x = fmaf(v0.x, w0, acc.x); acc.y = fmaf(v0.y, w0, acc.y);
    }
    float inv = (e > s) ? 1.0f / (float)(e - s) : 0.0f;
    float2* op = reinterpret_cast<float2*>(out + (size_t)gw * DOUT + lane * 2);
    float2 cur = *op;
    cur.x = fmaf(acc.x, inv, cur.x);
    cur.y = fmaf(acc.y, inv, cur.y);
    *op = cur;
}

// ---------------------------------------------------------------------------
// gemm1: x = relu( [h | hN] @ W1 + b1 )   M=10000, K=256, N=256
// BM=BN=64, BK=16, 64 threads, 8x8 microtile   (known-good R2 config)
// ---------------------------------------------------------------------------
__global__ __launch_bounds__(64)
void gemm1_kernel(const float* __restrict__ A1, const float* __restrict__ A2,
                  const float* __restrict__ W, const float* __restrict__ bias,
                  float* __restrict__ C) {
    constexpr int BM = 64, BN = 64, BK = 16, K = 256, K1 = 128, NT = 256;
    __shared__ float As[BK][BM];
    __shared__ float Bs[BK][BN];

    int tid  = threadIdx.x;
    int row0 = blockIdx.x * BM;
    int col0 = blockIdx.y * BN;

    int a_m  = row0 + tid;
    bool a_ok = (a_m < NNODES);

    int b_r0 = tid >> 4;           // 0..3
    int b_c4 = (tid & 15) * 4;     // 0..60

    int ty = tid >> 3, tx = tid & 7;
    int cm = ty * 8, cn = tx * 8;

    float acc[8][8] = {};

    for (int kb = 0; kb < K; kb += BK) {
        const float* Ab = (kb < K1) ? A1 : A2;
        int kloc = (kb < K1) ? kb : kb - K1;
        const float* arow = Ab + (size_t)a_m * K1 + kloc;
#pragma unroll
        for (int q = 0; q < 4; ++q) {
            float4 av = make_float4(0.f, 0.f, 0.f, 0.f);
            if (a_ok) av = *reinterpret_cast<const float4*>(arow + q * 4);
            As[q * 4 + 0][tid] = av.x;
            As[q * 4 + 1][tid] = av.y;
            As[q * 4 + 2][tid] = av.z;
            As[q * 4 + 3][tid] = av.w;
        }
#pragma unroll
        for (int q = 0; q < 4; ++q) {
            int kr = b_r0 + q * 4;  // 0..15
            *reinterpret_cast<float4*>(&Bs[kr][b_c4]) =
                *reinterpret_cast<const float4*>(W + (size_t)(kb + kr) * NT + col0 + b_c4);
        }
        __syncthreads();
#pragma unroll
        for (int kk = 0; kk < BK; ++kk) {
            float a[8], b[8];
            *reinterpret_cast<float4*>(a)     = *reinterpret_cast<const float4*>(&As[kk][cm]);
            *reinterpret_cast<float4*>(a + 4) = *reinterpret_cast<const float4*>(&As[kk][cm + 4]);
            *reinterpret_cast<float4*>(b)     = *reinterpret_cast<const float4*>(&Bs[kk][cn]);
            *reinterpret_cast<float4*>(b + 4) = *reinterpret_cast<const float4*>(&Bs[kk][cn + 4]);
#pragma unroll
            for (int i = 0; i < 8; ++i)
#pragma unroll
                for (int jj = 0; jj < 8; ++jj)
                    acc[i][jj] = fmaf(a[i], b[jj], acc[i][jj]);
        }
        __syncthreads();
    }

#pragma unroll
    for (int i = 0; i < 8; ++i) {
        int m = row0 + cm + i;
        if (m < NNODES) {
#pragma unroll
            for (int j0 = 0; j0 < 8; j0 += 4) {
                float4 o;
                o.x = fmaxf(acc[i][j0 + 0] + bias[col0 + cn + j0 + 0], 0.f);
                o.y = fmaxf(acc[i][j0 + 1] + bias[col0 + cn + j0 + 1], 0.f);
                o.z = fmaxf(acc[i][j0 + 2] + bias[col0 + cn + j0 + 2], 0.f);
                o.w = fmaxf(acc[i][j0 + 3] + bias[col0 + cn + j0 + 3], 0.f);
                *reinterpret_cast<float4*>(C + (size_t)m * NT + col0 + cn + j0) = o;
            }
        }
    }
}

// ---------------------------------------------------------------------------
// gemm2: blockIdx.y==0: out = x @ W2[0:256]   + b2   (fp32 -> d_out)
//        blockIdx.y==1: y   = x @ W2[256:512]        (fp16 -> g_yh)
// M=10000, K=256, N=64 each.  BM=BN=64, BK=16, 64 threads, 8x8 microtile
// ---------------------------------------------------------------------------
__global__ __launch_bounds__(64)
void gemm2_kernel(const float* __restrict__ A, const float* __restrict__ W2,
                  const float* __restrict__ bias, float* __restrict__ out) {
    constexpr int BM = 64, BN = 64, BK = 16, K = 256, KA = 256;
    __shared__ float As[BK][BM];
    __shared__ float Bs[BK][BN];

    int tid  = threadIdx.x;
    int row0 = blockIdx.x * BM;
    bool top = (blockIdx.y == 0);
    const float* W = top ? W2 : (W2 + (size_t)256 * DOUT);

    int a_m  = row0 + tid;
    bool a_ok = (a_m < NNODES);

    int b_r0 = tid >> 4;
    int b_c4 = (tid & 15) * 4;

    int ty = tid >> 3, tx = tid & 7;
    int cm = ty * 8, cn = tx * 8;

    float acc[8][8] = {};

    for (int kb = 0; kb < K; kb += BK) {
        const float* arow = A + (size_t)a_m * KA + kb;
#pragma unroll
        for (int q = 0; q < 4; ++q) {
            float4 av = make_float4(0.f, 0.f, 0.f, 0.f);
            if (a_ok) av = *reinterpret_cast<const float4*>(arow + q * 4);
            As[q * 4 + 0][tid] = av.x;
            As[q * 4 + 1][tid] = av.y;
            As[q * 4 + 2][tid] = av.z;
            As[q * 4 + 3][tid] = av.w;
        }
#pragma unroll
        for (int q = 0; q < 4; ++q) {
            int kr = b_r0 + q * 4;
            *reinterpret_cast<float4*>(&Bs[kr][b_c4]) =
                *reinterpret_cast<const float4*>(W + (size_t)(kb + kr) * DOUT + b_c4);
        }
        __syncthreads();
#pragma unroll
        for (int kk = 0; kk < BK; ++kk) {
            float a[8], b[8];
            *reinterpret_cast<float4*>(a)     = *reinterpret_cast<const float4*>(&As[kk][cm]);
            *reinterpret_cast<float4*>(a + 4) = *reinterpret_cast<const float4*>(&As[kk][cm + 4]);
            *reinterpret_cast<float4*>(b)     = *reinterpret_cast<const float4*>(&Bs[kk][cn]);
            *reinterpret_cast<float4*>(b + 4) = *reinterpret_cast<const float4*>(&Bs[kk][cn + 4]);
#pragma unroll
            for (int i = 0; i < 8; ++i)
#pragma unroll
                for (int jj = 0; jj < 8; ++jj)
                    acc[i][jj] = fmaf(a[i], b[jj], acc[i][jj]);
        }
        __syncthreads();
    }

#pragma unroll
    for (int i = 0; i < 8; ++i) {
        int m = row0 + cm + i;
        if (m < NNODES) {
#pragma unroll
            for (int j0 = 0; j0 < 8; j0 += 4) {
                if (top) {
                    float4 o;
                    o.x = acc[i][j0 + 0] + bias[cn + j0 + 0];
                    o.y = acc[i][j0 + 1] + bias[cn + j0 + 1];
                    o.z = acc[i][j0 + 2] + bias[cn + j0 + 2];
                    o.w = acc[i][j0 + 3] + bias[cn + j0 + 3];
                    *reinterpret_cast<float4*>(out + (size_t)m * DOUT + cn + j0) = o;
                } else {
                    __half2 h0 = __floats2half2_rn(acc[i][j0 + 0], acc[i][j0 + 1]);
                    __half2 h1 = __floats2half2_rn(acc[i][j0 + 2], acc[i][j0 + 3]);
                    uint2 pk;
                    pk.x = *reinterpret_cast<unsigned*>(&h0);
                    pk.y = *reinterpret_cast<unsigned*>(&h1);
                    *reinterpret_cast<uint2*>(g_yh + (size_t)m * DOUT + cn + j0) = pk;
                }
            }
        }
    }
}

// ---------------------------------------------------------------------------
extern "C" void kernel_launch(void* const* d_in, const int* in_sizes, int n_in,
                              void* d_out, int out_size) {
    const float* h   = (const float*)d_in[0];
    const float* w   = (const float*)d_in[1];
    const int*   src = (const int*)  d_in[2];
    const int*   dst = (const int*)  d_in[3];
    const float* W1  = (const float*)d_in[4];
    const float* b1  = (const float*)d_in[5];
    const float* W2  = (const float*)d_in[6];
    const float* b2  = (const float*)d_in[7];
    float* out = (float*)d_out;

    float *hN, *x;
    cudaGetSymbolAddress((void**)&hN, g_hN);
    cudaGetSymbolAddress((void**)&x,  g_x);

    // CSR build (by dst)
    zero_cnt_kernel<<<(NNODES + 255) / 256, 256>>>();
    count_rank_kernel<<<(NE + 255) / 256, 256>>>(dst);
    scan_kernel<<<1, 1024>>>();
    fill_kernel<<<(NE + 255) / 256, 256>>>(src, dst, w);

    // h -> fp16 (gather operand)
    convert_h_kernel<<<(NNODES * DIN / 2 + 255) / 256, 256>>>(h);

    // layer 1: gather (mean, normalized, fp16 reads) then GEMM+relu
    gather1_kernel<<<(NNODES * 32 + 255) / 256, 256>>>();
    dim3 g1((NNODES + 63) / 64, DHID / 64);
    gemm1_kernel<<<g1, 64>>>(h, hN, W1, b1, x);

    // layer 2 via linearity: out = x@W2_top + b2 ; yh = x@W2_bot (fp16) ; out += agg(yh)
    dim3 g2((NNODES + 63) / 64, 2);
    gemm2_kernel<<<g2, 64>>>(x, W2, b2, out);
    gather2_kernel<<<(NNODES * 32 + 255) / 256, 256>>>(out);
}

// round 8
// speedup vs baseline: 2.6490x; 1.5072x over previous
#include <cuda_runtime.h>
#include <cuda_fp16.h>
#include <mma.h>
using namespace nvcuda;

static constexpr int NNODES = 10000;
static constexpr int NE     = 640000;
static constexpr int DIN    = 128;
static constexpr int DHID   = 256;
static constexpr int DOUT   = 64;

// ---- scratch (__device__ globals: allocation-free rule) ----
__device__ int    g_cnt[NNODES];
__device__ int    g_off[NNODES + 1];
__device__ int    g_rank[NE];
__device__ int2   g_edges[NE];             // (src, w bits) grouped by dst
__device__ __half g_hh [NNODES * DIN];     // h in fp16
__device__ __half g_hNh[NNODES * DIN];     // layer-1 mean aggregate, fp16
__device__ __half g_xh [NNODES * DHID];    // layer-1 output (post relu), fp16
__device__ __half g_yh [NNODES * DOUT];    // x @ W2_bot, fp16
__device__ __half g_W1h[2 * DIN * DHID];   // W1 fp16 [256 x 256]
__device__ __half g_W2h[2 * DHID * DOUT];  // W2 fp16 [512 x 64]

// ---------------------------------------------------------------------------
// CSR build: zero -> count(+rank) -> scan -> fill(no atomics)
// ---------------------------------------------------------------------------
__global__ void zero_cnt_kernel() {
    int i = blockIdx.x * blockDim.x + threadIdx.x;
    if (i < NNODES) g_cnt[i] = 0;
}

__global__ void count_rank_kernel(const int* __restrict__ dst) {
    int e = blockIdx.x * blockDim.x + threadIdx.x;
    if (e < NE) g_rank[e] = atomicAdd(&g_cnt[dst[e]], 1);
}

__global__ void scan_kernel() {
    __shared__ int sh[1024];
    constexpr int CH = 10;                // 1024*10 >= 10000
    int t = threadIdx.x;
    int base = t * CH;
    int loc[CH];
    int sum = 0;
#pragma unroll
    for (int i = 0; i < CH; ++i) {
        int idx = base + i;
        int v = (idx < NNODES) ? g_cnt[idx] : 0;
        loc[i] = sum;
        sum += v;
    }
    sh[t] = sum;
    __syncthreads();
    for (int d = 1; d < 1024; d <<= 1) {
        int v = (t >= d) ? sh[t - d] : 0;
        __syncthreads();
        sh[t] += v;
        __syncthreads();
    }
    int excl = (t > 0) ? sh[t - 1] : 0;
#pragma unroll
    for (int i = 0; i < CH; ++i) {
        int idx = base + i;
        if (idx < NNODES) g_off[idx] = excl + loc[i];
    }
    if (t == 1023) g_off[NNODES] = sh[1023];
}

__global__ void fill_kernel(const int* __restrict__ src, const int* __restrict__ dst,
                            const float* __restrict__ w) {
    int e = blockIdx.x * blockDim.x + threadIdx.x;
    if (e < NE) {
        int pos = g_off[dst[e]] + g_rank[e];
        g_edges[pos] = make_int2(src[e], __float_as_int(w[e]));
    }
}

// ---------------------------------------------------------------------------
// fp32 -> fp16 convert (n must be even)
// ---------------------------------------------------------------------------
__global__ void cvt_kernel(const float* __restrict__ src, __half* __restrict__ dst, int n2) {
    int i = blockIdx.x * blockDim.x + threadIdx.x;
    if (i < n2) {
        float2 v = reinterpret_cast<const float2*>(src)[i];
        reinterpret_cast<__half2*>(dst)[i] = __floats2half2_rn(v.x, v.y);
    }
}

// ---------------------------------------------------------------------------
// gather1: hNh[n] = fp16( (1/deg) * sum h[src]*w )   (D=128, fp16 reads/writes)
// ---------------------------------------------------------------------------
__global__ __launch_bounds__(256)
void gather1_kernel() {
    int gw = (blockIdx.x * blockDim.x + threadIdx.x) >> 5;
    if (gw >= NNODES) return;
    int lane = threadIdx.x & 31;
    int s = g_off[gw], e = g_off[gw + 1];
    float4 acc = make_float4(0.f, 0.f, 0.f, 0.f);
    int j = s;
    for (; j + 3 < e; j += 4) {
        int2 e0 = g_edges[j];
        int2 e1 = g_edges[j + 1];
        int2 e2 = g_edges[j + 2];
        int2 e3 = g_edges[j + 3];
        uint2 r0 = *reinterpret_cast<const uint2*>(g_hh + (size_t)e0.x * DIN + lane * 4);
        uint2 r1 = *reinterpret_cast<const uint2*>(g_hh + (size_t)e1.x * DIN + lane * 4);
        uint2 r2 = *reinterpret_cast<const uint2*>(g_hh + (size_t)e2.x * DIN + lane * 4);
        uint2 r3 = *reinterpret_cast<const uint2*>(g_hh + (size_t)e3.x * DIN + lane * 4);
        float w0 = __int_as_float(e0.y), w1 = __int_as_float(e1.y);
        float w2 = __int_as_float(e2.y), w3 = __int_as_float(e3.y);
        {
            float2 a = __half22float2(*reinterpret_cast<__half2*>(&r0.x));
            float2 b = __half22float2(*reinterpret_cast<__half2*>(&r0.y));
            acc.x = fmaf(a.x, w0, acc.x); acc.y = fmaf(a.y, w0, acc.y);
            acc.z = fmaf(b.x, w0, acc.z); acc.w = fmaf(b.y, w0, acc.w);
        }
        {
            float2 a = __half22float2(*reinterpret_cast<__half2*>(&r1.x));
            float2 b = __half22float2(*reinterpret_cast<__half2*>(&r1.y));
            acc.x = fmaf(a.x, w1, acc.x); acc.y = fmaf(a.y, w1, acc.y);
            acc.z = fmaf(b.x, w1, acc.z); acc.w = fmaf(b.y, w1, acc.w);
        }
        {
            float2 a = __half22float2(*reinterpret_cast<__half2*>(&r2.x));
            float2 b = __half22float2(*reinterpret_cast<__half2*>(&r2.y));
            acc.x = fmaf(a.x, w2, acc.x); acc.y = fmaf(a.y, w2, acc.y);
            acc.z = fmaf(b.x, w2, acc.z); acc.w = fmaf(b.y, w2, acc.w);
        }
        {
            float2 a = __half22float2(*reinterpret_cast<__half2*>(&r3.x));
            float2 b = __half22float2(*reinterpret_cast<__half2*>(&r3.y));
            acc.x = fmaf(a.x, w3, acc.x); acc.y = fmaf(a.y, w3, acc.y);
            acc.z = fmaf(b.x, w3, acc.z); acc.w = fmaf(b.y, w3, acc.w);
        }
    }
    for (; j < e; ++j) {
        int2 e0 = g_edges[j];
        float w0 = __int_as_float(e0.y);
        uint2 r0 = *reinterpret_cast<const uint2*>(g_hh + (size_t)e0.x * DIN + lane * 4);
        float2 a = __half22float2(*reinterpret_cast<__half2*>(&r0.x));
        float2 b = __half22float2(*reinterpret_cast<__half2*>(&r0.y));
        acc.x = fmaf(a.x, w0, acc.x); acc.y = fmaf(a.y, w0, acc.y);
        acc.z = fmaf(b.x, w0, acc.z); acc.w = fmaf(b.y, w0, acc.w);
    }
    float inv = (e > s) ? 1.0f / (float)(e - s) : 0.0f;
    __half2 p0 = __floats2half2_rn(acc.x * inv, acc.y * inv);
    __half2 p1 = __floats2half2_rn(acc.z * inv, acc.w * inv);
    uint2 pk;
    pk.x = *reinterpret_cast<unsigned*>(&p0);
    pk.y = *reinterpret_cast<unsigned*>(&p1);
    *reinterpret_cast<uint2*>(g_hNh + (size_t)gw * DIN + lane * 4) = pk;
}

// ---------------------------------------------------------------------------
// gather2: out[n] += (1/deg) * sum y[src]*w     (D=64, fp16 reads)
// ---------------------------------------------------------------------------
__global__ __launch_bounds__(256)
void gather2_kernel(float* __restrict__ out) {
    int gw = (blockIdx.x * blockDim.x + threadIdx.x) >> 5;
    if (gw >= NNODES) return;
    int lane = threadIdx.x & 31;
    int s = g_off[gw], e = g_off[gw + 1];
    float2 acc = make_float2(0.f, 0.f);
    int j = s;
    for (; j + 3 < e; j += 4) {
        int2 e0 = g_edges[j];
        int2 e1 = g_edges[j + 1];
        int2 e2 = g_edges[j + 2];
        int2 e3 = g_edges[j + 3];
        __half2 p0 = *reinterpret_cast<const __half2*>(g_yh + (size_t)e0.x * DOUT + lane * 2);
        __half2 p1 = *reinterpret_cast<const __half2*>(g_yh + (size_t)e1.x * DOUT + lane * 2);
        __half2 p2 = *reinterpret_cast<const __half2*>(g_yh + (size_t)e2.x * DOUT + lane * 2);
        __half2 p3 = *reinterpret_cast<const __half2*>(g_yh + (size_t)e3.x * DOUT + lane * 2);
        float w0 = __int_as_float(e0.y), w1 = __int_as_float(e1.y);
        float w2 = __int_as_float(e2.y), w3 = __int_as_float(e3.y);
        float2 v0 = __half22float2(p0), v1 = __half22float2(p1);
        float2 v2 = __half22float2(p2), v3 = __half22float2(p3);
        acc.x = fmaf(v0.x, w0, acc.x); acc.y = fmaf(v0.y, w0, acc.y);
        acc.x = fmaf(v1.x, w1, acc.x); acc.y = fmaf(v1.y, w1, acc.y);
        acc.x = fmaf(v2.x, w2, acc.x); acc.y = fmaf(v2.y, w2, acc.y);
        acc.x = fmaf(v3.x, w3, acc.x); acc.y = fmaf(v3.y, w3, acc.y);
    }
    for (; j < e; ++j) {
        int2 e0 = g_edges[j];
        float w0 = __int_as_float(e0.y);
        float2 v0 = __half22float2(*reinterpret_cast<const __half2*>(g_yh + (size_t)e0.x * DOUT + lane * 2));
        acc.x = fmaf(v0.x, w0, acc.x); acc.y = fmaf(v0.y, w0, acc.y);
    }
    float inv = (e > s) ? 1.0f / (float)(e - s) : 0.0f;
    float2* op = reinterpret_cast<float2*>(out + (size_t)gw * DOUT + lane * 2);
    float2 cur = *op;
    cur.x = fmaf(acc.x, inv, cur.x);
    cur.y = fmaf(acc.y, inv, cur.y);
    *op = cur;
}

// ---------------------------------------------------------------------------
// gemm1 (HMMA): xh = fp16( relu( [hh | hNh] @ W1h + b1 ) )
// M=10000, K=256, N=256.  CTA: 128 thr (4 warps), BM=BN=BK=64.
// Each warp: 32x32 output = 2x2 wmma 16x16x16 tiles, fp32 accum.
// smem: As[64][72] h, Bs[64][72] h  (union with Cs[64][72] f32 for epilogue)
// ---------------------------------------------------------------------------
__global__ __launch_bounds__(128)
void gemm1_f16_kernel(const float* __restrict__ bias) {
    constexpr int LDS = 72;   // halves (16B-aligned rows: 144B)
    __shared__ __align__(16) char sm[64 * LDS * 4];   // 18432 B
    __half* As = reinterpret_cast<__half*>(sm);              // [64][72]
    __half* Bs = reinterpret_cast<__half*>(sm) + 64 * LDS;   // [64][72]
    float*  Cs = reinterpret_cast<float*>(sm);               // [64][72]

    int tid  = threadIdx.x;
    int wid  = tid >> 5;
    int row0 = blockIdx.x * 64;
    int col0 = blockIdx.y * 64;
    int wy = wid >> 1, wx = wid & 1;

    int lr = tid >> 1;          // 0..63 tile row
    int lq = (tid & 1) * 32;    // halves col offset: 0 or 32

    wmma::fragment<wmma::accumulator, 16, 16, 16, float> acc[2][2];
#pragma unroll
    for (int i = 0; i < 2; ++i)
#pragma unroll
        for (int j = 0; j < 2; ++j)
            wmma::fill_fragment(acc[i][j], 0.0f);

    int  a_m  = row0 + lr;
    bool a_ok = (a_m < NNODES);

    for (int kb = 0; kb < 256; kb += 64) {
        // A tile: rows of [hh | hNh]; each 64-wide k-block lies in one half
        const __half* abase = (kb < 128)
            ? (g_hh  + (size_t)a_m * DIN + kb)
            : (g_hNh + (size_t)a_m * DIN + (kb - 128));
        uint4 av[4] = {};
        if (a_ok) {
#pragma unroll
            for (int q = 0; q < 4; ++q)
                av[q] = reinterpret_cast<const uint4*>(abase + lq)[q];
        }
#pragma unroll
        for (int q = 0; q < 4; ++q)
            reinterpret_cast<uint4*>(As + lr * LDS + lq)[q] = av[q];

        // B tile: W1h rows kb..kb+63, cols col0..col0+63
        const __half* wb = g_W1h + (size_t)(kb + lr) * DHID + col0 + lq;
#pragma unroll
        for (int q = 0; q < 4; ++q)
            reinterpret_cast<uint4*>(Bs + lr * LDS + lq)[q] =
                reinterpret_cast<const uint4*>(wb)[q];

        __syncthreads();

#pragma unroll
        for (int ks = 0; ks < 4; ++ks) {
            wmma::fragment<wmma::matrix_a, 16, 16, 16, __half, wmma::row_major> af[2];
            wmma::fragment<wmma::matrix_b, 16, 16, 16, __half, wmma::row_major> bf[2];
            wmma::load_matrix_sync(af[0], As + (wy * 32 +  0) * LDS + ks * 16, LDS);
            wmma::load_matrix_sync(af[1], As + (wy * 32 + 16) * LDS + ks * 16, LDS);
            wmma::load_matrix_sync(bf[0], Bs + (ks * 16) * LDS + wx * 32 +  0, LDS);
            wmma::load_matrix_sync(bf[1], Bs + (ks * 16) * LDS + wx * 32 + 16, LDS);
#pragma unroll
            for (int i = 0; i < 2; ++i)
#pragma unroll
                for (int j = 0; j < 2; ++j)
                    wmma::mma_sync(acc[i][j], af[i], bf[j], acc[i][j]);
        }
        __syncthreads();
    }

    // epilogue via smem (Cs aliases As/Bs; safe after final sync)
#pragma unroll
    for (int i = 0; i < 2; ++i)
#pragma unroll
        for (int j = 0; j < 2; ++j)
            wmma::store_matrix_sync(Cs + (wy * 32 + i * 16) * LDS + wx * 32 + j * 16,
                                    acc[i][j], LDS, wmma::mem_row_major);
    __syncthreads();

    if (a_ok) {
#pragma unroll
        for (int c = 0; c < 32; c += 2) {
            int col = col0 + lq + c;
            float v0 = fmaxf(Cs[lr * LDS + lq + c]     + bias[col],     0.f);
            float v1 = fmaxf(Cs[lr * LDS + lq + c + 1] + bias[col + 1], 0.f);
            __half2 p = __floats2half2_rn(v0, v1);
            *reinterpret_cast<__half2*>(g_xh + (size_t)a_m * DHID + col) = p;
        }
    }
}

// ---------------------------------------------------------------------------
// gemm2 (HMMA): blockIdx.y==0: out = xh @ W2h[0:256] + b2  (fp32 -> d_out)
//               blockIdx.y==1: yh  = xh @ W2h[256:512]     (fp16 -> g_yh)
// M=10000, K=256, N=64.  Same CTA structure as gemm1.
// ---------------------------------------------------------------------------
__global__ __launch_bounds__(128)
void gemm2_f16_kernel(const float* __restrict__ bias, float* __restrict__ out) {
    constexpr int LDS = 72;
    __shared__ __align__(16) char sm[64 * LDS * 4];
    __half* As = reinterpret_cast<__half*>(sm);
    __half* Bs = reinterpret_cast<__half*>(sm) + 64 * LDS;
    float*  Cs = reinterpret_cast<float*>(sm);

    int tid  = threadIdx.x;
    int wid  = tid >> 5;
    int row0 = blockIdx.x * 64;
    bool top = (blockIdx.y == 0);
    const __half* W = g_W2h + (top ? 0 : (size_t)DHID * DOUT);

    int wy = wid >> 1, wx = wid & 1;
    int lr = tid >> 1;
    int lq = (tid & 1) * 32;

    wmma::fragment<wmma::accumulator, 16, 16, 16, float> acc[2][2];
#pragma unroll
    for (int i = 0; i < 2; ++i)
#pragma unroll
        for (int j = 0; j < 2; ++j)
            wmma::fill_fragment(acc[i][j], 0.0f);

    int  a_m  = row0 + lr;
    bool a_ok = (a_m < NNODES);

    for (int kb = 0; kb < 256; kb += 64) {
        const __half* abase = g_xh + (size_t)a_m * DHID + kb;
        uint4 av[4] = {};
        if (a_ok) {
#pragma unroll
            for (int q = 0; q < 4; ++q)
                av[q] = reinterpret_cast<const uint4*>(abase + lq)[q];
        }
#pragma unroll
        for (int q = 0; q < 4; ++q)
            reinterpret_cast<uint4*>(As + lr * LDS + lq)[q] = av[q];

        // B tile: rows kb..kb+63 of W (64 cols = full N)
        const __half* wb = W + (size_t)(kb + lr) * DOUT + lq;
#pragma unroll
        for (int q = 0; q < 4; ++q)
            reinterpret_cast<uint4*>(Bs + lr * LDS + lq)[q] =
                reinterpret_cast<const uint4*>(wb)[q];

        __syncthreads();

#pragma unroll
        for (int ks = 0; ks < 4; ++ks) {
            wmma::fragment<wmma::matrix_a, 16, 16, 16, __half, wmma::row_major> af[2];
            wmma::fragment<wmma::matrix_b, 16, 16, 16, __half, wmma::row_major> bf[2];
            wmma::load_matrix_sync(af[0], As + (wy * 32 +  0) * LDS + ks * 16, LDS);
            wmma::load_matrix_sync(af[1], As + (wy * 32 + 16) * LDS + ks * 16, LDS);
            wmma::load_matrix_sync(bf[0], Bs + (ks * 16) * LDS + wx * 32 +  0, LDS);
            wmma::load_matrix_sync(bf[1], Bs + (ks * 16) * LDS + wx * 32 + 16, LDS);
#pragma unroll
            for (int i = 0; i < 2; ++i)
#pragma unroll
                for (int j = 0; j < 2; ++j)
                    wmma::mma_sync(acc[i][j], af[i], bf[j], acc[i][j]);
        }
        __syncthreads();
    }

#pragma unroll
    for (int i = 0; i < 2; ++i)
#pragma unroll
        for (int j = 0; j < 2; ++j)
            wmma::store_matrix_sync(Cs + (wy * 32 + i * 16) * LDS + wx * 32 + j * 16,
                                    acc[i][j], LDS, wmma::mem_row_major);
    __syncthreads();

    if (a_ok) {
        if (top) {
#pragma unroll
            for (int c = 0; c < 32; c += 4) {
                int col = lq + c;
                float4 o;
                o.x = Cs[lr * LDS + col + 0] + bias[col + 0];
                o.y = Cs[lr * LDS + col + 1] + bias[col + 1];
                o.z = Cs[lr * LDS + col + 2] + bias[col + 2];
                o.w = Cs[lr * LDS + col + 3] + bias[col + 3];
                *reinterpret_cast<float4*>(out + (size_t)a_m * DOUT + col) = o;
            }
        } else {
#pragma unroll
            for (int c = 0; c < 32; c += 2) {
                int col = lq + c;
                __half2 p = __floats2half2_rn(Cs[lr * LDS + col], Cs[lr * LDS + col + 1]);
                *reinterpret_cast<__half2*>(g_yh + (size_t)a_m * DOUT + col) = p;
            }
        }
    }
}

// ---------------------------------------------------------------------------
extern "C" void kernel_launch(void* const* d_in, const int* in_sizes, int n_in,
                              void* d_out, int out_size) {
    const float* h   = (const float*)d_in[0];
    const float* w   = (const float*)d_in[1];
    const int*   src = (const int*)  d_in[2];
    const int*   dst = (const int*)  d_in[3];
    const float* W1  = (const float*)d_in[4];
    const float* b1  = (const float*)d_in[5];
    const float* W2  = (const float*)d_in[6];
    const float* b2  = (const float*)d_in[7];
    float* out = (float*)d_out;

    __half *hh, *w1h, *w2h;
    cudaGetSymbolAddress((void**)&hh,  g_hh);
    cudaGetSymbolAddress((void**)&w1h, g_W1h);
    cudaGetSymbolAddress((void**)&w2h, g_W2h);

    // CSR build (by dst)
    zero_cnt_kernel<<<(NNODES + 255) / 256, 256>>>();
    count_rank_kernel<<<(NE + 255) / 256, 256>>>(dst);
    scan_kernel<<<1, 1024>>>();
    fill_kernel<<<(NE + 255) / 256, 256>>>(src, dst, w);

    // fp16 conversions (h, W1, W2)
    cvt_kernel<<<(NNODES * DIN / 2 + 255) / 256, 256>>>(h,  hh,  NNODES * DIN / 2);
    cvt_kernel<<<(2 * DIN * DHID / 2 + 255) / 256, 256>>>(W1, w1h, 2 * DIN * DHID / 2);
    cvt_kernel<<<(2 * DHID * DOUT / 2 + 255) / 256, 256>>>(W2, w2h, 2 * DHID * DOUT / 2);

    // layer 1: gather (fp16) then HMMA GEMM + relu -> xh (fp16)
    gather1_kernel<<<(NNODES * 32 + 255) / 256, 256>>>();
    dim3 g1((NNODES + 63) / 64, DHID / 64);
    gemm1_f16_kernel<<<g1, 128>>>(b1);

    // layer 2 via linearity: out = xh@W2_top + b2 ; yh = xh@W2_bot ; out += agg(yh)
    dim3 g2((NNODES + 63) / 64, 2);
    gemm2_f16_kernel<<<g2, 128>>>(b2, out);
    gather2_kernel<<<(NNODES * 32 + 255) / 256, 256>>>(out);
}

// round 9
// speedup vs baseline: 2.7171x; 1.0257x over previous
#include <cuda_runtime.h>
#include <cuda_fp16.h>
#include <mma.h>
using namespace nvcuda;

static constexpr int NNODES = 10000;
static constexpr int NE     = 640000;
static constexpr int DIN    = 128;
static constexpr int DHID   = 256;
static constexpr int DOUT   = 64;

static constexpr int H_HALF2  = NNODES * DIN / 2;        // 640000 == NE
static constexpr int W1_HALF2 = 2 * DIN * DHID / 2;      // 32768
static constexpr int W2_HALF2 = 2 * DHID * DOUT / 2;     // 16384

// ---- scratch (__device__ globals: allocation-free rule) ----
__device__ int    g_cnt[NNODES];           // zero-init; invariant: 0 at kernel_launch entry
__device__ int    g_off[NNODES + 1];
__device__ int    g_rank[NE];
__device__ int2   g_edges[NE];             // (src, w bits) grouped by dst
__device__ __half g_hh [NNODES * DIN];     // h in fp16
__device__ __half g_hNh[NNODES * DIN];     // layer-1 mean aggregate, fp16
__device__ __half g_xh [NNODES * DHID];    // layer-1 output (post relu), fp16
__device__ __half g_yh [NNODES * DOUT];    // x @ W2_bot, fp16
__device__ __half g_W1h[2 * DIN * DHID];   // W1 fp16 [256 x 256]
__device__ __half g_W2h[2 * DHID * DOUT];  // W2 fp16 [512 x 64]

// ---------------------------------------------------------------------------
// CSR build: count(+rank) -> scan(+reset cnt) -> fill(+fp16 converts)
// ---------------------------------------------------------------------------
__global__ void count_rank_kernel(const int* __restrict__ dst) {
    int e = blockIdx.x * blockDim.x + threadIdx.x;
    if (e < NE) g_rank[e] = atomicAdd(&g_cnt[dst[e]], 1);
}

__global__ void scan_kernel() {
    __shared__ int sh[1024];
    constexpr int CH = 10;                // 1024*10 >= 10000
    int t = threadIdx.x;
    int base = t * CH;
    int loc[CH];
    int sum = 0;
#pragma unroll
    for (int i = 0; i < CH; ++i) {
        int idx = base + i;
        int v = 0;
        if (idx < NNODES) {
            v = g_cnt[idx];
            g_cnt[idx] = 0;               // reset for next invocation (invariant)
        }
        loc[i] = sum;
        sum += v;
    }
    sh[t] = sum;
    __syncthreads();
    for (int d = 1; d < 1024; d <<= 1) {
        int v = (t >= d) ? sh[t - d] : 0;
        __syncthreads();
        sh[t] += v;
        __syncthreads();
    }
    int excl = (t > 0) ? sh[t - 1] : 0;
#pragma unroll
    for (int i = 0; i < CH; ++i) {
        int idx = base + i;
        if (idx < NNODES) g_off[idx] = excl + loc[i];
    }
    if (t == 1023) g_off[NNODES] = sh[1023];
}

// fill edges + all fp32->fp16 conversions in one launch.
// threads [0, NE): edge fill AND h convert (H_HALF2 == NE)
// threads [NE, NE+W1_HALF2): W1 convert
// threads [NE+W1_HALF2, NE+W1_HALF2+W2_HALF2): W2 convert
__global__ void fill_cvt_kernel(const int* __restrict__ src, const int* __restrict__ dst,
                                const float* __restrict__ w,
                                const float* __restrict__ h,
                                const float* __restrict__ W1,
                                const float* __restrict__ W2) {
    int e = blockIdx.x * blockDim.x + threadIdx.x;
    if (e < NE) {
        int pos = g_off[dst[e]] + g_rank[e];
        g_edges[pos] = make_int2(src[e], __float_as_int(w[e]));
        // h convert (same thread range)
        float2 v = reinterpret_cast<const float2*>(h)[e];
        reinterpret_cast<__half2*>(g_hh)[e] = __floats2half2_rn(v.x, v.y);
    } else {
        int i = e - NE;
        if (i < W1_HALF2) {
            float2 v = reinterpret_cast<const float2*>(W1)[i];
            reinterpret_cast<__half2*>(g_W1h)[i] = __floats2half2_rn(v.x, v.y);
        } else if (i < W1_HALF2 + W2_HALF2) {
            int k = i - W1_HALF2;
            float2 v = reinterpret_cast<const float2*>(W2)[k];
            reinterpret_cast<__half2*>(g_W2h)[k] = __floats2half2_rn(v.x, v.y);
        }
    }
}

// ---------------------------------------------------------------------------
// gather1: hNh[n] = fp16( (1/deg) * sum h[src]*w )   (D=128, fp16 reads/writes)
// ---------------------------------------------------------------------------
__global__ __launch_bounds__(256)
void gather1_kernel() {
    int gw = (blockIdx.x * blockDim.x + threadIdx.x) >> 5;
    if (gw >= NNODES) return;
    int lane = threadIdx.x & 31;
    int s = g_off[gw], e = g_off[gw + 1];
    float4 acc = make_float4(0.f, 0.f, 0.f, 0.f);
    int j = s;
    for (; j + 3 < e; j += 4) {
        int2 e0 = g_edges[j];
        int2 e1 = g_edges[j + 1];
        int2 e2 = g_edges[j + 2];
        int2 e3 = g_edges[j + 3];
        uint2 r0 = *reinterpret_cast<const uint2*>(g_hh + (size_t)e0.x * DIN + lane * 4);
        uint2 r1 = *reinterpret_cast<const uint2*>(g_hh + (size_t)e1.x * DIN + lane * 4);
        uint2 r2 = *reinterpret_cast<const uint2*>(g_hh + (size_t)e2.x * DIN + lane * 4);
        uint2 r3 = *reinterpret_cast<const uint2*>(g_hh + (size_t)e3.x * DIN + lane * 4);
        float w0 = __int_as_float(e0.y), w1 = __int_as_float(e1.y);
        float w2 = __int_as_float(e2.y), w3 = __int_as_float(e3.y);
        {
            float2 a = __half22float2(*reinterpret_cast<__half2*>(&r0.x));
            float2 b = __half22float2(*reinterpret_cast<__half2*>(&r0.y));
            acc.x = fmaf(a.x, w0, acc.x); acc.y = fmaf(a.y, w0, acc.y);
            acc.z = fmaf(b.x, w0, acc.z); acc.w = fmaf(b.y, w0, acc.w);
        }
        {
            float2 a = __half22float2(*reinterpret_cast<__half2*>(&r1.x));
            float2 b = __half22float2(*reinterpret_cast<__half2*>(&r1.y));
            acc.x = fmaf(a.x, w1, acc.x); acc.y = fmaf(a.y, w1, acc.y);
            acc.z = fmaf(b.x, w1, acc.z); acc.w = fmaf(b.y, w1, acc.w);
        }
        {
            float2 a = __half22float2(*reinterpret_cast<__half2*>(&r2.x));
            float2 b = __half22float2(*reinterpret_cast<__half2*>(&r2.y));
            acc.x = fmaf(a.x, w2, acc.x); acc.y = fmaf(a.y, w2, acc.y);
            acc.z = fmaf(b.x, w2, acc.z); acc.w = fmaf(b.y, w2, acc.w);
        }
        {
            float2 a = __half22float2(*reinterpret_cast<__half2*>(&r3.x));
            float2 b = __half22float2(*reinterpret_cast<__half2*>(&r3.y));
            acc.x = fmaf(a.x, w3, acc.x); acc.y = fmaf(a.y, w3, acc.y);
            acc.z = fmaf(b.x, w3, acc.z); acc.w = fmaf(b.y, w3, acc.w);
        }
    }
    for (; j < e; ++j) {
        int2 e0 = g_edges[j];
        float w0 = __int_as_float(e0.y);
        uint2 r0 = *reinterpret_cast<const uint2*>(g_hh + (size_t)e0.x * DIN + lane * 4);
        float2 a = __half22float2(*reinterpret_cast<__half2*>(&r0.x));
        float2 b = __half22float2(*reinterpret_cast<__half2*>(&r0.y));
        acc.x = fmaf(a.x, w0, acc.x); acc.y = fmaf(a.y, w0, acc.y);
        acc.z = fmaf(b.x, w0, acc.z); acc.w = fmaf(b.y, w0, acc.w);
    }
    float inv = (e > s) ? 1.0f / (float)(e - s) : 0.0f;
    __half2 p0 = __floats2half2_rn(acc.x * inv, acc.y * inv);
    __half2 p1 = __floats2half2_rn(acc.z * inv, acc.w * inv);
    uint2 pk;
    pk.x = *reinterpret_cast<unsigned*>(&p0);
    pk.y = *reinterpret_cast<unsigned*>(&p1);
    *reinterpret_cast<uint2*>(g_hNh + (size_t)gw * DIN + lane * 4) = pk;
}

// ---------------------------------------------------------------------------
// gather2: out[n] += (1/deg) * sum y[src]*w     (D=64, fp16 reads)
// ---------------------------------------------------------------------------
__global__ __launch_bounds__(256)
void gather2_kernel(float* __restrict__ out) {
    int gw = (blockIdx.x * blockDim.x + threadIdx.x) >> 5;
    if (gw >= NNODES) return;
    int lane = threadIdx.x & 31;
    int s = g_off[gw], e = g_off[gw + 1];
    float2 acc = make_float2(0.f, 0.f);
    int j = s;
    for (; j + 3 < e; j += 4) {
        int2 e0 = g_edges[j];
        int2 e1 = g_edges[j + 1];
        int2 e2 = g_edges[j + 2];
        int2 e3 = g_edges[j + 3];
        __half2 p0 = *reinterpret_cast<const __half2*>(g_yh + (size_t)e0.x * DOUT + lane * 2);
        __half2 p1 = *reinterpret_cast<const __half2*>(g_yh + (size_t)e1.x * DOUT + lane * 2);
        __half2 p2 = *reinterpret_cast<const __half2*>(g_yh + (size_t)e2.x * DOUT + lane * 2);
        __half2 p3 = *reinterpret_cast<const __half2*>(g_yh + (size_t)e3.x * DOUT + lane * 2);
        float w0 = __int_as_float(e0.y), w1 = __int_as_float(e1.y);
        float w2 = __int_as_float(e2.y), w3 = __int_as_float(e3.y);
        float2 v0 = __half22float2(p0), v1 = __half22float2(p1);
        float2 v2 = __half22float2(p2), v3 = __half22float2(p3);
        acc.x = fmaf(v0.x, w0, acc.x); acc.y = fmaf(v0.y, w0, acc.y);
        acc.x = fmaf(v1.x, w1, acc.x); acc.y = fmaf(v1.y, w1, acc.y);
        acc.x = fmaf(v2.x, w2, acc.x); acc.y = fmaf(v2.y, w2, acc.y);
        acc.x = fmaf(v3.x, w3, acc.x); acc.y = fmaf(v3.y, w3, acc.y);
    }
    for (; j < e; ++j) {
        int2 e0 = g_edges[j];
        float w0 = __int_as_float(e0.y);
        float2 v0 = __half22float2(*reinterpret_cast<const __half2*>(g_yh + (size_t)e0.x * DOUT + lane * 2));
        acc.x = fmaf(v0.x, w0, acc.x); acc.y = fmaf(v0.y, w0, acc.y);
    }
    float inv = (e > s) ? 1.0f / (float)(e - s) : 0.0f;
    float2* op = reinterpret_cast<float2*>(out + (size_t)gw * DOUT + lane * 2);
    float2 cur = *op;
    cur.x = fmaf(acc.x, inv, cur.x);
    cur.y = fmaf(acc.y, inv, cur.y);
    *op = cur;
}

// ---------------------------------------------------------------------------
// gemm1 (HMMA): xh = fp16( relu( [hh | hNh] @ W1h + b1 ) )
// M=10000, K=256, N=256.  CTA: 128 thr (4 warps), BM=BN=BK=64.
// ---------------------------------------------------------------------------
__global__ __launch_bounds__(128)
void gemm1_f16_kernel(const float* __restrict__ bias) {
    constexpr int LDS = 72;   // halves (16B-aligned rows: 144B)
    __shared__ __align__(16) char sm[64 * LDS * 4];   // 18432 B
    __half* As = reinterpret_cast<__half*>(sm);              // [64][72]
    __half* Bs = reinterpret_cast<__half*>(sm) + 64 * LDS;   // [64][72]
    float*  Cs = reinterpret_cast<float*>(sm);               // [64][72]

    int tid  = threadIdx.x;
    int wid  = tid >> 5;
    int row0 = blockIdx.x * 64;
    int col0 = blockIdx.y * 64;
    int wy = wid >> 1, wx = wid & 1;

    int lr = tid >> 1;          // 0..63 tile row
    int lq = (tid & 1) * 32;    // halves col offset: 0 or 32

    wmma::fragment<wmma::accumulator, 16, 16, 16, float> acc[2][2];
#pragma unroll
    for (int i = 0; i < 2; ++i)
#pragma unroll
        for (int j = 0; j < 2; ++j)
            wmma::fill_fragment(acc[i][j], 0.0f);

    int  a_m  = row0 + lr;
    bool a_ok = (a_m < NNODES);

    for (int kb = 0; kb < 256; kb += 64) {
        const __half* abase = (kb < 128)
            ? (g_hh  + (size_t)a_m * DIN + kb)
            : (g_hNh + (size_t)a_m * DIN + (kb - 128));
        uint4 av[4] = {};
        if (a_ok) {
#pragma unroll
            for (int q = 0; q < 4; ++q)
                av[q] = reinterpret_cast<const uint4*>(abase + lq)[q];
        }
#pragma unroll
        for (int q = 0; q < 4; ++q)
            reinterpret_cast<uint4*>(As + lr * LDS + lq)[q] = av[q];

        const __half* wb = g_W1h + (size_t)(kb + lr) * DHID + col0 + lq;
#pragma unroll
        for (int q = 0; q < 4; ++q)
            reinterpret_cast<uint4*>(Bs + lr * LDS + lq)[q] =
                reinterpret_cast<const uint4*>(wb)[q];

        __syncthreads();

#pragma unroll
        for (int ks = 0; ks < 4; ++ks) {
            wmma::fragment<wmma::matrix_a, 16, 16, 16, __half, wmma::row_major> af[2];
            wmma::fragment<wmma::matrix_b, 16, 16, 16, __half, wmma::row_major> bf[2];
            wmma::load_matrix_sync(af[0], As + (wy * 32 +  0) * LDS + ks * 16, LDS);
            wmma::load_matrix_sync(af[1], As + (wy * 32 + 16) * LDS + ks * 16, LDS);
            wmma::load_matrix_sync(bf[0], Bs + (ks * 16) * LDS + wx * 32 +  0, LDS);
            wmma::load_matrix_sync(bf[1], Bs + (ks * 16) * LDS + wx * 32 + 16, LDS);
#pragma unroll
            for (int i = 0; i < 2; ++i)
#pragma unroll
                for (int j = 0; j < 2; ++j)
                    wmma::mma_sync(acc[i][j], af[i], bf[j], acc[i][j]);
        }
        __syncthreads();
    }

#pragma unroll
    for (int i = 0; i < 2; ++i)
#pragma unroll
        for (int j = 0; j < 2; ++j)
            wmma::store_matrix_sync(Cs + (wy * 32 + i * 16) * LDS + wx * 32 + j * 16,
                                    acc[i][j], LDS, wmma::mem_row_major);
    __syncthreads();

    if (a_ok) {
#pragma unroll
        for (int c = 0; c < 32; c += 2) {
            int col = col0 + lq + c;
            float v0 = fmaxf(Cs[lr * LDS + lq + c]     + bias[col],     0.f);
            float v1 = fmaxf(Cs[lr * LDS + lq + c + 1] + bias[col + 1], 0.f);
            __half2 p = __floats2half2_rn(v0, v1);
            *reinterpret_cast<__half2*>(g_xh + (size_t)a_m * DHID + col) = p;
        }
    }
}

// ---------------------------------------------------------------------------
// gemm2 (HMMA): blockIdx.y==0: out = xh @ W2h[0:256] + b2  (fp32 -> d_out)
//               blockIdx.y==1: yh  = xh @ W2h[256:512]     (fp16 -> g_yh)
// ---------------------------------------------------------------------------
__global__ __launch_bounds__(128)
void gemm2_f16_kernel(const float* __restrict__ bias, float* __restrict__ out) {
    constexpr int LDS = 72;
    __shared__ __align__(16) char sm[64 * LDS * 4];
    __half* As = reinterpret_cast<__half*>(sm);
    __half* Bs = reinterpret_cast<__half*>(sm) + 64 * LDS;
    float*  Cs = reinterpret_cast<float*>(sm);

    int tid  = threadIdx.x;
    int wid  = tid >> 5;
    int row0 = blockIdx.x * 64;
    bool top = (blockIdx.y == 0);
    const __half* W = g_W2h + (top ? 0 : (size_t)DHID * DOUT);

    int wy = wid >> 1, wx = wid & 1;
    int lr = tid >> 1;
    int lq = (tid & 1) * 32;

    wmma::fragment<wmma::accumulator, 16, 16, 16, float> acc[2][2];
#pragma unroll
    for (int i = 0; i < 2; ++i)
#pragma unroll
        for (int j = 0; j < 2; ++j)
            wmma::fill_fragment(acc[i][j], 0.0f);

    int  a_m  = row0 + lr;
    bool a_ok = (a_m < NNODES);

    for (int kb = 0; kb < 256; kb += 64) {
        const __half* abase = g_xh + (size_t)a_m * DHID + kb;
        uint4 av[4] = {};
        if (a_ok) {
#pragma unroll
            for (int q = 0; q < 4; ++q)
                av[q] = reinterpret_cast<const uint4*>(abase + lq)[q];
        }
#pragma unroll
        for (int q = 0; q < 4; ++q)
            reinterpret_cast<uint4*>(As + lr * LDS + lq)[q] = av[q];

        const __half* wb = W + (size_t)(kb + lr) * DOUT + lq;
#pragma unroll
        for (int q = 0; q < 4; ++q)
            reinterpret_cast<uint4*>(Bs + lr * LDS + lq)[q] =
                reinterpret_cast<const uint4*>(wb)[q];

        __syncthreads();

#pragma unroll
        for (int ks = 0; ks < 4; ++ks) {
            wmma::fragment<wmma::matrix_a, 16, 16, 16, __half, wmma::row_major> af[2];
            wmma::fragment<wmma::matrix_b, 16, 16, 16, __half, wmma::row_major> bf[2];
            wmma::load_matrix_sync(af[0], As + (wy * 32 +  0) * LDS + ks * 16, LDS);
            wmma::load_matrix_sync(af[1], As + (wy * 32 + 16) * LDS + ks * 16, LDS);
            wmma::load_matrix_sync(bf[0], Bs + (ks * 16) * LDS + wx * 32 +  0, LDS);
            wmma::load_matrix_sync(bf[1], Bs + (ks * 16) * LDS + wx * 32 + 16, LDS);
#pragma unroll
            for (int i = 0; i < 2; ++i)
#pragma unroll
                for (int j = 0; j < 2; ++j)
                    wmma::mma_sync(acc[i][j], af[i], bf[j], acc[i][j]);
        }
        __syncthreads();
    }

#pragma unroll
    for (int i = 0; i < 2; ++i)
#pragma unroll
        for (int j = 0; j < 2; ++j)
            wmma::store_matrix_sync(Cs + (wy * 32 + i * 16) * LDS + wx * 32 + j * 16,
                                    acc[i][j], LDS, wmma::mem_row_major);
    __syncthreads();

    if (a_ok) {
        if (top) {
#pragma unroll
            for (int c = 0; c < 32; c += 4) {
                int col = lq + c;
                float4 o;
                o.x = Cs[lr * LDS + col + 0] + bias[col + 0];
                o.y = Cs[lr * LDS + col + 1] + bias[col + 1];
                o.z = Cs[lr * LDS + col + 2] + bias[col + 2];
                o.w = Cs[lr * LDS + col + 3] + bias[col + 3];
                *reinterpret_cast<float4*>(out + (size_t)a_m * DOUT + col) = o;
            }
        } else {
#pragma unroll
            for (int c = 0; c < 32; c += 2) {
                int col = lq + c;
                __half2 p = __floats2half2_rn(Cs[lr * LDS + col], Cs[lr * LDS + col + 1]);
                *reinterpret_cast<__half2*>(g_yh + (size_t)a_m * DOUT + col) = p;
            }
        }
    }
}

// ---------------------------------------------------------------------------
extern "C" void kernel_launch(void* const* d_in, const int* in_sizes, int n_in,
                              void* d_out, int out_size) {
    const float* h   = (const float*)d_in[0];
    const float* w   = (const float*)d_in[1];
    const int*   src = (const int*)  d_in[2];
    const int*   dst = (const int*)  d_in[3];
    const float* W1  = (const float*)d_in[4];
    const float* b1  = (const float*)d_in[5];
    const float* W2  = (const float*)d_in[6];
    const float* b2  = (const float*)d_in[7];
    float* out = (float*)d_out;

    // CSR build (by dst); g_cnt==0 invariant maintained by scan_kernel's reset
    count_rank_kernel<<<(NE + 255) / 256, 256>>>(dst);
    scan_kernel<<<1, 1024>>>();
    fill_cvt_kernel<<<(NE + W1_HALF2 + W2_HALF2 + 255) / 256, 256>>>(src, dst, w, h, W1, W2);

    // layer 1: gather (fp16) then HMMA GEMM + relu -> xh (fp16)
    gather1_kernel<<<(NNODES * 32 + 255) / 256, 256>>>();
    dim3 g1((NNODES + 63) / 64, DHID / 64);
    gemm1_f16_kernel<<<g1, 128>>>(b1);

    // layer 2 via linearity: out = xh@W2_top + b2 ; yh = xh@W2_bot ; out += agg(yh)
    dim3 g2((NNODES + 63) / 64, 2);
    gemm2_f16_kernel<<<g2, 128>>>(b2, out);
    gather2_kernel<<<(NNODES * 32 + 255) / 256, 256>>>(out);
}

// round 10
// speedup vs baseline: 2.7622x; 1.0166x over previous
#include <cuda_runtime.h>
#include <cuda_fp16.h>
#include <mma.h>
using namespace nvcuda;

static constexpr int NNODES = 10000;
static constexpr int NE     = 640000;
static constexpr int DIN    = 128;
static constexpr int DHID   = 256;
static constexpr int DOUT   = 64;

static constexpr int W1_HALF2 = 2 * DIN * DHID / 2;      // 32768
static constexpr int W2_HALF2 = 2 * DHID * DOUT / 2;     // 16384

// ---- scratch (__device__ globals: allocation-free rule) ----
__device__ int    g_cnt[NNODES];           // zero-init; invariant: 0 at kernel_launch entry
__device__ int    g_off[NNODES + 1];
__device__ int    g_rank[NE];
__device__ int2   g_edges[NE];             // (src, w bits) grouped by dst
__device__ __half g_hh [NNODES * DIN];     // h in fp16
__device__ __half g_hNh[NNODES * DIN];     // layer-1 mean aggregate, fp16
__device__ __half g_xh [NNODES * DHID];    // layer-1 output (post relu), fp16
__device__ __half g_yh [NNODES * DOUT];    // x @ W2_bot, fp16
__device__ __half g_W1h[2 * DIN * DHID];   // W1 fp16 [256 x 256]
__device__ __half g_W2h[2 * DHID * DOUT];  // W2 fp16 [512 x 64]

// ---------------------------------------------------------------------------
// CSR build: count(+rank) -> scan(+reset cnt) -> fill(+fp16 converts)
// ---------------------------------------------------------------------------
__global__ void count_rank_kernel(const int* __restrict__ dst) {
    int e = blockIdx.x * blockDim.x + threadIdx.x;
    if (e < NE) g_rank[e] = atomicAdd(&g_cnt[dst[e]], 1);
}

__global__ void scan_kernel() {
    __shared__ int sh[1024];
    constexpr int CH = 10;                // 1024*10 >= 10000
    int t = threadIdx.x;
    int base = t * CH;
    int loc[CH];
    int sum = 0;
#pragma unroll
    for (int i = 0; i < CH; ++i) {
        int idx = base + i;
        int v = 0;
        if (idx < NNODES) {
            v = g_cnt[idx];
            g_cnt[idx] = 0;               // reset for next invocation (invariant)
        }
        loc[i] = sum;
        sum += v;
    }
    sh[t] = sum;
    __syncthreads();
    for (int d = 1; d < 1024; d <<= 1) {
        int v = (t >= d) ? sh[t - d] : 0;
        __syncthreads();
        sh[t] += v;
        __syncthreads();
    }
    int excl = (t > 0) ? sh[t - 1] : 0;
#pragma unroll
    for (int i = 0; i < CH; ++i) {
        int idx = base + i;
        if (idx < NNODES) g_off[idx] = excl + loc[i];
    }
    if (t == 1023) g_off[NNODES] = sh[1023];
}

// fill edges + all fp32->fp16 conversions in one launch.
__global__ void fill_cvt_kernel(const int* __restrict__ src, const int* __restrict__ dst,
                                const float* __restrict__ w,
                                const float* __restrict__ h,
                                const float* __restrict__ W1,
                                const float* __restrict__ W2) {
    int e = blockIdx.x * blockDim.x + threadIdx.x;
    if (e < NE) {
        int pos = g_off[dst[e]] + g_rank[e];
        g_edges[pos] = make_int2(src[e], __float_as_int(w[e]));
        float2 v = reinterpret_cast<const float2*>(h)[e];   // NE == NNODES*DIN/2
        reinterpret_cast<__half2*>(g_hh)[e] = __floats2half2_rn(v.x, v.y);
    } else {
        int i = e - NE;
        if (i < W1_HALF2) {
            float2 v = reinterpret_cast<const float2*>(W1)[i];
            reinterpret_cast<__half2*>(g_W1h)[i] = __floats2half2_rn(v.x, v.y);
        } else if (i < W1_HALF2 + W2_HALF2) {
            int k = i - W1_HALF2;
            float2 v = reinterpret_cast<const float2*>(W2)[k];
            reinterpret_cast<__half2*>(g_W2h)[k] = __floats2half2_rn(v.x, v.y);
        }
    }
}

// ---------------------------------------------------------------------------
// helpers
// ---------------------------------------------------------------------------
__device__ __forceinline__ void acc_uint4_f16(float* acc, uint4 r, float w) {
    float2 p0 = __half22float2(*reinterpret_cast<__half2*>(&r.x));
    float2 p1 = __half22float2(*reinterpret_cast<__half2*>(&r.y));
    float2 p2 = __half22float2(*reinterpret_cast<__half2*>(&r.z));
    float2 p3 = __half22float2(*reinterpret_cast<__half2*>(&r.w));
    acc[0] = fmaf(p0.x, w, acc[0]); acc[1] = fmaf(p0.y, w, acc[1]);
    acc[2] = fmaf(p1.x, w, acc[2]); acc[3] = fmaf(p1.y, w, acc[3]);
    acc[4] = fmaf(p2.x, w, acc[4]); acc[5] = fmaf(p2.y, w, acc[5]);
    acc[6] = fmaf(p3.x, w, acc[6]); acc[7] = fmaf(p3.y, w, acc[7]);
}

// ---------------------------------------------------------------------------
// gather1: hNh[n] = fp16( (1/deg) * sum h[src]*w )   (D=128)
// one warp per node; 2 lane-groups of 16, each lane loads uint4 (8 halves)
// -> one warp-load advances 2 edges; unroll x2 -> 4 edges/iter
// ---------------------------------------------------------------------------
__global__ __launch_bounds__(256)
void gather1_kernel() {
    int gw = (blockIdx.x * blockDim.x + threadIdx.x) >> 5;
    if (gw >= NNODES) return;
    int lane = threadIdx.x & 31;
    int grp  = lane >> 4;          // 0 or 1
    int sub  = lane & 15;          // column block: halves [sub*8, sub*8+8)
    int s = g_off[gw], e = g_off[gw + 1];
    float acc[8] = {};

    int j = s;
    for (; j + 3 < e; j += 4) {
        int2 ea = g_edges[j + grp];
        int2 eb = g_edges[j + 2 + grp];
        uint4 ra = *reinterpret_cast<const uint4*>(g_hh + (size_t)ea.x * DIN + sub * 8);
        uint4 rb = *reinterpret_cast<const uint4*>(g_hh + (size_t)eb.x * DIN + sub * 8);
        acc_uint4_f16(acc, ra, __int_as_float(ea.y));
        acc_uint4_f16(acc, rb, __int_as_float(eb.y));
    }
    for (; j < e; j += 2) {
        if (j + grp < e) {
            int2 ea = g_edges[j + grp];
            uint4 ra = *reinterpret_cast<const uint4*>(g_hh + (size_t)ea.x * DIN + sub * 8);
            acc_uint4_f16(acc, ra, __int_as_float(ea.y));
        }
    }

    // combine the two groups: lane i (<16) += lane i+16
#pragma unroll
    for (int k = 0; k < 8; ++k)
        acc[k] += __shfl_down_sync(0xffffffffu, acc[k], 16);

    if (lane < 16) {
        float inv = (e > s) ? 1.0f / (float)(e - s) : 0.0f;
        __half2 q0 = __floats2half2_rn(acc[0] * inv, acc[1] * inv);
        __half2 q1 = __floats2half2_rn(acc[2] * inv, acc[3] * inv);
        __half2 q2 = __floats2half2_rn(acc[4] * inv, acc[5] * inv);
        __half2 q3 = __floats2half2_rn(acc[6] * inv, acc[7] * inv);
        uint4 pk;
        pk.x = *reinterpret_cast<unsigned*>(&q0);
        pk.y = *reinterpret_cast<unsigned*>(&q1);
        pk.z = *reinterpret_cast<unsigned*>(&q2);
        pk.w = *reinterpret_cast<unsigned*>(&q3);
        *reinterpret_cast<uint4*>(g_hNh + (size_t)gw * DIN + sub * 8) = pk;
    }
}

// ---------------------------------------------------------------------------
// gather2: out[n] += (1/deg) * sum y[src]*w     (D=64)
// one warp per node; 4 lane-groups of 8, each lane loads uint4 (8 halves)
// -> one warp-load advances 4 edges
// ---------------------------------------------------------------------------
__global__ __launch_bounds__(256)
void gather2_kernel(float* __restrict__ out) {
    int gw = (blockIdx.x * blockDim.x + threadIdx.x) >> 5;
    if (gw >= NNODES) return;
    int lane = threadIdx.x & 31;
    int grp  = lane >> 3;          // 0..3
    int sub  = lane & 7;           // halves [sub*8, sub*8+8)
    int s = g_off[gw], e = g_off[gw + 1];
    float acc[8] = {};

    int j = s;
    for (; j + 7 < e; j += 8) {
        int2 ea = g_edges[j + grp];
        int2 eb = g_edges[j + 4 + grp];
        uint4 ra = *reinterpret_cast<const uint4*>(g_yh + (size_t)ea.x * DOUT + sub * 8);
        uint4 rb = *reinterpret_cast<const uint4*>(g_yh + (size_t)eb.x * DOUT + sub * 8);
        acc_uint4_f16(acc, ra, __int_as_float(ea.y));
        acc_uint4_f16(acc, rb, __int_as_float(eb.y));
    }
    for (; j < e; j += 4) {
        if (j + grp < e) {
            int2 ea = g_edges[j + grp];
            uint4 ra = *reinterpret_cast<const uint4*>(g_yh + (size_t)ea.x * DOUT + sub * 8);
            acc_uint4_f16(acc, ra, __int_as_float(ea.y));
        }
    }

    // combine 4 groups -> lanes 0..7
#pragma unroll
    for (int k = 0; k < 8; ++k) {
        acc[k] += __shfl_down_sync(0xffffffffu, acc[k], 16);
        acc[k] += __shfl_down_sync(0xffffffffu, acc[k], 8);
    }

    if (lane < 8) {
        float inv = (e > s) ? 1.0f / (float)(e - s) : 0.0f;
        float* op = out + (size_t)gw * DOUT + sub * 8;
        float4 c0 = *reinterpret_cast<float4*>(op);
        float4 c1 = *reinterpret_cast<float4*>(op + 4);
        c0.x = fmaf(acc[0], inv, c0.x); c0.y = fmaf(acc[1], inv, c0.y);
        c0.z = fmaf(acc[2], inv, c0.z); c0.w = fmaf(acc[3], inv, c0.w);
        c1.x = fmaf(acc[4], inv, c1.x); c1.y = fmaf(acc[5], inv, c1.y);
        c1.z = fmaf(acc[6], inv, c1.z); c1.w = fmaf(acc[7], inv, c1.w);
        *reinterpret_cast<float4*>(op)     = c0;
        *reinterpret_cast<float4*>(op + 4) = c1;
    }
}

// ---------------------------------------------------------------------------
// gemm1 (HMMA): xh = fp16( relu( [hh | hNh] @ W1h + b1 ) )
// M=10000, K=256, N=256.  CTA: 128 thr (4 warps), BM=BN=BK=64.
// ---------------------------------------------------------------------------
__global__ __launch_bounds__(128)
void gemm1_f16_kernel(const float* __restrict__ bias) {
    constexpr int LDS = 72;   // halves (16B-aligned rows: 144B)
    __shared__ __align__(16) char sm[64 * LDS * 4];   // 18432 B
    __half* As = reinterpret_cast<__half*>(sm);              // [64][72]
    __half* Bs = reinterpret_cast<__half*>(sm) + 64 * LDS;   // [64][72]
    float*  Cs = reinterpret_cast<float*>(sm);               // [64][72]

    int tid  = threadIdx.x;
    int wid  = tid >> 5;
    int row0 = blockIdx.x * 64;
    int col0 = blockIdx.y * 64;
    int wy = wid >> 1, wx = wid & 1;

    int lr = tid >> 1;          // 0..63 tile row
    int lq = (tid & 1) * 32;    // halves col offset: 0 or 32

    wmma::fragment<wmma::accumulator, 16, 16, 16, float> acc[2][2];
#pragma unroll
    for (int i = 0; i < 2; ++i)
#pragma unroll
        for (int j = 0; j < 2; ++j)
            wmma::fill_fragment(acc[i][j], 0.0f);

    int  a_m  = row0 + lr;
    bool a_ok = (a_m < NNODES);

    for (int kb = 0; kb < 256; kb += 64) {
        const __half* abase = (kb < 128)
            ? (g_hh  + (size_t)a_m * DIN + kb)
            : (g_hNh + (size_t)a_m * DIN + (kb - 128));
        uint4 av[4] = {};
        if (a_ok) {
#pragma unroll
            for (int q = 0; q < 4; ++q)
                av[q] = reinterpret_cast<const uint4*>(abase + lq)[q];
        }
#pragma unroll
        for (int q = 0; q < 4; ++q)
            reinterpret_cast<uint4*>(As + lr * LDS + lq)[q] = av[q];

        const __half* wb = g_W1h + (size_t)(kb + lr) * DHID + col0 + lq;
#pragma unroll
        for (int q = 0; q < 4; ++q)
            reinterpret_cast<uint4*>(Bs + lr * LDS + lq)[q] =
                reinterpret_cast<const uint4*>(wb)[q];

        __syncthreads();

#pragma unroll
        for (int ks = 0; ks < 4; ++ks) {
            wmma::fragment<wmma::matrix_a, 16, 16, 16, __half, wmma::row_major> af[2];
            wmma::fragment<wmma::matrix_b, 16, 16, 16, __half, wmma::row_major> bf[2];
            wmma::load_matrix_sync(af[0], As + (wy * 32 +  0) * LDS + ks * 16, LDS);
            wmma::load_matrix_sync(af[1], As + (wy * 32 + 16) * LDS + ks * 16, LDS);
            wmma::load_matrix_sync(bf[0], Bs + (ks * 16) * LDS + wx * 32 +  0, LDS);
            wmma::load_matrix_sync(bf[1], Bs + (ks * 16) * LDS + wx * 32 + 16, LDS);
#pragma unroll
            for (int i = 0; i < 2; ++i)
#pragma unroll
                for (int j = 0; j < 2; ++j)
                    wmma::mma_sync(acc[i][j], af[i], bf[j], acc[i][j]);
        }
        __syncthreads();
    }

#pragma unroll
    for (int i = 0; i < 2; ++i)
#pragma unroll
        for (int j = 0; j < 2; ++j)
            wmma::store_matrix_sync(Cs + (wy * 32 + i * 16) * LDS + wx * 32 + j * 16,
                                    acc[i][j], LDS, wmma::mem_row_major);
    __syncthreads();

    if (a_ok) {
#pragma unroll
        for (int c = 0; c < 32; c += 2) {
            int col = col0 + lq + c;
            float v0 = fmaxf(Cs[lr * LDS + lq + c]     + bias[col],     0.f);
            float v1 = fmaxf(Cs[lr * LDS + lq + c + 1] + bias[col + 1], 0.f);
            __half2 p = __floats2half2_rn(v0, v1);
            *reinterpret_cast<__half2*>(g_xh + (size_t)a_m * DHID + col) = p;
        }
    }
}

// ---------------------------------------------------------------------------
// gemm2 (HMMA): blockIdx.y==0: out = xh @ W2h[0:256] + b2  (fp32 -> d_out)
//               blockIdx.y==1: yh  = xh @ W2h[256:512]     (fp16 -> g_yh)
// ---------------------------------------------------------------------------
__global__ __launch_bounds__(128)
void gemm2_f16_kernel(const float* __restrict__ bias, float* __restrict__ out) {
    constexpr int LDS = 72;
    __shared__ __align__(16) char sm[64 * LDS * 4];
    __half* As = reinterpret_cast<__half*>(sm);
    __half* Bs = reinterpret_cast<__half*>(sm) + 64 * LDS;
    float*  Cs = reinterpret_cast<float*>(sm);

    int tid  = threadIdx.x;
    int wid  = tid >> 5;
    int row0 = blockIdx.x * 64;
    bool top = (blockIdx.y == 0);
    const __half* W = g_W2h + (top ? 0 : (size_t)DHID * DOUT);

    int wy = wid >> 1, wx = wid & 1;
    int lr = tid >> 1;
    int lq = (tid & 1) * 32;

    wmma::fragment<wmma::accumulator, 16, 16, 16, float> acc[2][2];
#pragma unroll
    for (int i = 0; i < 2; ++i)
#pragma unroll
        for (int j = 0; j < 2; ++j)
            wmma::fill_fragment(acc[i][j], 0.0f);

    int  a_m  = row0 + lr;
    bool a_ok = (a_m < NNODES);

    for (int kb = 0; kb < 256; kb += 64) {
        const __half* abase = g_xh + (size_t)a_m * DHID + kb;
        uint4 av[4] = {};
        if (a_ok) {
#pragma unroll
            for (int q = 0; q < 4; ++q)
                av[q] = reinterpret_cast<const uint4*>(abase + lq)[q];
        }
#pragma unroll
        for (int q = 0; q < 4; ++q)
            reinterpret_cast<uint4*>(As + lr * LDS + lq)[q] = av[q];

        const __half* wb = W + (size_t)(kb + lr) * DOUT + lq;
#pragma unroll
        for (int q = 0; q < 4; ++q)
            reinterpret_cast<uint4*>(Bs + lr * LDS + lq)[q] =
                reinterpret_cast<const uint4*>(wb)[q];

        __syncthreads();

#pragma unroll
        for (int ks = 0; ks < 4; ++ks) {
            wmma::fragment<wmma::matrix_a, 16, 16, 16, __half, wmma::row_major> af[2];
            wmma::fragment<wmma::matrix_b, 16, 16, 16, __half, wmma::row_major> bf[2];
            wmma::load_matrix_sync(af[0], As + (wy * 32 +  0) * LDS + ks * 16, LDS);
            wmma::load_matrix_sync(af[1], As + (wy * 32 + 16) * LDS + ks * 16, LDS);
            wmma::load_matrix_sync(bf[0], Bs + (ks * 16) * LDS + wx * 32 +  0, LDS);
            wmma::load_matrix_sync(bf[1], Bs + (ks * 16) * LDS + wx * 32 + 16, LDS);
#pragma unroll
            for (int i = 0; i < 2; ++i)
#pragma unroll
                for (int j = 0; j < 2; ++j)
                    wmma::mma_sync(acc[i][j], af[i], bf[j], acc[i][j]);
        }
        __syncthreads();
    }

#pragma unroll
    for (int i = 0; i < 2; ++i)
#pragma unroll
        for (int j = 0; j < 2; ++j)
            wmma::store_matrix_sync(Cs + (wy * 32 + i * 16) * LDS + wx * 32 + j * 16,
                                    acc[i][j], LDS, wmma::mem_row_major);
    __syncthreads();

    if (a_ok) {
        if (top) {
#pragma unroll
            for (int c = 0; c < 32; c += 4) {
                int col = lq + c;
                float4 o;
                o.x = Cs[lr * LDS + col + 0] + bias[col + 0];
                o.y = Cs[lr * LDS + col + 1] + bias[col + 1];
                o.z = Cs[lr * LDS + col + 2] + bias[col + 2];
                o.w = Cs[lr * LDS + col + 3] + bias[col + 3];
                *reinterpret_cast<float4*>(out + (size_t)a_m * DOUT + col) = o;
            }
        } else {
#pragma unroll
            for (int c = 0; c < 32; c += 2) {
                int col = lq + c;
                __half2 p = __floats2half2_rn(Cs[lr * LDS + col], Cs[lr * LDS + col + 1]);
                *reinterpret_cast<__half2*>(g_yh + (size_t)a_m * DOUT + col) = p;
            }
        }
    }
}

// ---------------------------------------------------------------------------
extern "C" void kernel_launch(void* const* d_in, const int* in_sizes, int n_in,
                              void* d_out, int out_size) {
    const float* h   = (const float*)d_in[0];
    const float* w   = (const float*)d_in[1];
    const int*   src = (const int*)  d_in[2];
    const int*   dst = (const int*)  d_in[3];
    const float* W1  = (const float*)d_in[4];
    const float* b1  = (const float*)d_in[5];
    const float* W2  = (const float*)d_in[6];
    const float* b2  = (const float*)d_in[7];
    float* out = (float*)d_out;

    // CSR build (by dst); g_cnt==0 invariant maintained by scan_kernel's reset
    count_rank_kernel<<<(NE + 255) / 256, 256>>>(dst);
    scan_kernel<<<1, 1024>>>();
    fill_cvt_kernel<<<(NE + W1_HALF2 + W2_HALF2 + 255) / 256, 256>>>(src, dst, w, h, W1, W2);

    // layer 1: gather (fp16) then HMMA GEMM + relu -> xh (fp16)
    gather1_kernel<<<(NNODES * 32 + 255) / 256, 256>>>();
    dim3 g1((NNODES + 63) / 64, DHID / 64);
    gemm1_f16_kernel<<<g1, 128>>>(b1);

    // layer 2 via linearity: out = xh@W2_top + b2 ; yh = xh@W2_bot ; out += agg(yh)
    dim3 g2((NNODES + 63) / 64, 2);
    gemm2_f16_kernel<<<g2, 128>>>(b2, out);
    gather2_kernel<<<(NNODES * 32 + 255) / 256, 256>>>(out);
}